// round 2
// baseline (speedup 1.0000x reference)
#include <cuda_runtime.h>
#include <math.h>

#define D     1536
#define S_HID 2048
#define S_ENC 256
#define T_TOT 2304
#define NH    24
#define HD    64

// Scratch (allocation-free rule: __device__ globals)
__device__ float g_Q [S_HID * D];
__device__ float g_K [T_TOT * D];
__device__ float g_V [T_TOT * D];
__device__ float g_AO[S_HID * D];

// ----------------------------------------------------------------------------
// GEMM: C[M,N] = A[M,K] @ W[N,K]^T + bias   (torch Linear, NT, inner-product)
// 64x64 tile, BK=32, 256 threads, 4x4 per thread, smem stored transposed
// ([k][m]) so compute reads are float4 and conflict-free.
// ----------------------------------------------------------------------------
__global__ __launch_bounds__(256) void gemm_nt_bias(
    const float* __restrict__ A, const float* __restrict__ W,
    const float* __restrict__ bias, float* __restrict__ C,
    int M, int N, int K)
{
    __shared__ float As[32][64];
    __shared__ float Ws[32][64];
    const int bm = blockIdx.y * 64, bn = blockIdx.x * 64;
    const int tid = threadIdx.x;
    const int tx = tid & 15, ty = tid >> 4;

    float acc[4][4] = {};

    for (int k0 = 0; k0 < K; k0 += 32) {
        #pragma unroll
        for (int l = 0; l < 2; l++) {
            int idx = tid + l * 256;          // 512 float4 per tile
            int row = idx >> 3;
            int c4  = (idx & 7) * 4;
            float4 av = *(const float4*)(A + (size_t)(bm + row) * K + k0 + c4);
            As[c4 + 0][row] = av.x; As[c4 + 1][row] = av.y;
            As[c4 + 2][row] = av.z; As[c4 + 3][row] = av.w;
            float4 wv = *(const float4*)(W + (size_t)(bn + row) * K + k0 + c4);
            Ws[c4 + 0][row] = wv.x; Ws[c4 + 1][row] = wv.y;
            Ws[c4 + 2][row] = wv.z; Ws[c4 + 3][row] = wv.w;
        }
        __syncthreads();
        #pragma unroll
        for (int kk = 0; kk < 32; kk++) {
            float4 a4 = *(const float4*)&As[kk][ty * 4];
            float4 b4 = *(const float4*)&Ws[kk][tx * 4];
            float av[4] = {a4.x, a4.y, a4.z, a4.w};
            float bv[4] = {b4.x, b4.y, b4.z, b4.w};
            #pragma unroll
            for (int i = 0; i < 4; i++)
                #pragma unroll
                for (int j = 0; j < 4; j++)
                    acc[i][j] += av[i] * bv[j];
        }
        __syncthreads();
    }

    #pragma unroll
    for (int i = 0; i < 4; i++) {
        float4 o;
        o.x = acc[i][0] + bias[bn + tx * 4 + 0];
        o.y = acc[i][1] + bias[bn + tx * 4 + 1];
        o.z = acc[i][2] + bias[bn + tx * 4 + 2];
        o.w = acc[i][3] + bias[bn + tx * 4 + 3];
        *(float4*)(C + (size_t)(bm + ty * 4 + i) * N + bn + tx * 4) = o;
    }
}

// ----------------------------------------------------------------------------
// Per-head RMSNorm in place. One warp per (token,head) row of 64.
// ----------------------------------------------------------------------------
__global__ __launch_bounds__(256) void rmsnorm_heads(
    float* __restrict__ X, const float* __restrict__ w, int ntasks)
{
    int task = (blockIdx.x * blockDim.x + threadIdx.x) >> 5;
    int lane = threadIdx.x & 31;
    if (task >= ntasks) return;
    int row = task / NH;
    int h   = task % NH;
    float* p = X + (size_t)row * D + h * HD;
    float2 v = ((float2*)p)[lane];
    float ss = v.x * v.x + v.y * v.y;
    #pragma unroll
    for (int o = 16; o; o >>= 1) ss += __shfl_xor_sync(0xffffffffu, ss, o);
    float r = rsqrtf(ss * (1.0f / HD) + 1e-6f);
    v.x *= r * w[2 * lane];
    v.y *= r * w[2 * lane + 1];
    ((float2*)p)[lane] = v;
}

// ----------------------------------------------------------------------------
// Flash attention, fp32. Block = (q-tile of 64 rows) x head. 256 threads.
// Online softmax over 36 kv-tiles of 64. Q pre-scaled by 1/sqrt(HD).
// ----------------------------------------------------------------------------
struct FlashSmem {
    float Qst[HD][64];   // [d][r], scaled
    float Kst[HD][64];   // [d][c]
    float Vs [64][HD];   // [k][d]
    float Pst[64][65];   // [k][r]
    float m[64], l[64], alpha[64];
    float red[64][17];
};

__global__ __launch_bounds__(256) void flash_attn(
    const float* __restrict__ Qg, const float* __restrict__ Kg,
    const float* __restrict__ Vg, const float* __restrict__ mask,
    float* __restrict__ Og)
{
    extern __shared__ char smem_raw[];
    FlashSmem& sm = *reinterpret_cast<FlashSmem*>(smem_raw);

    const int h   = blockIdx.y;
    const int q0  = blockIdx.x * 64;
    const int tid = threadIdx.x;
    const int tx  = tid & 15, ty = tid >> 4;
    const float scale = 0.125f;   // 64^-0.5

    #pragma unroll
    for (int l = 0; l < 4; l++) {
        int idx = tid + l * 256;
        int row = idx >> 4;
        int c4  = (idx & 15) * 4;
        float4 qv = *(const float4*)(Qg + (size_t)(q0 + row) * D + h * HD + c4);
        sm.Qst[c4 + 0][row] = qv.x * scale;
        sm.Qst[c4 + 1][row] = qv.y * scale;
        sm.Qst[c4 + 2][row] = qv.z * scale;
        sm.Qst[c4 + 3][row] = qv.w * scale;
    }
    if (tid < 64) { sm.m[tid] = -1e30f; sm.l[tid] = 0.0f; }

    float o[4][4] = {};

    for (int t = 0; t < T_TOT / 64; t++) {
        __syncthreads();   // protect Kst/Vs/Pst from previous iter's readers
        #pragma unroll
        for (int l = 0; l < 4; l++) {
            int idx = tid + l * 256;
            int row = idx >> 4;
            int c4  = (idx & 15) * 4;
            float4 kv = *(const float4*)(Kg + (size_t)(t * 64 + row) * D + h * HD + c4);
            sm.Kst[c4 + 0][row] = kv.x; sm.Kst[c4 + 1][row] = kv.y;
            sm.Kst[c4 + 2][row] = kv.z; sm.Kst[c4 + 3][row] = kv.w;
            float4 vv = *(const float4*)(Vg + (size_t)(t * 64 + row) * D + h * HD + c4);
            *(float4*)&sm.Vs[row][c4] = vv;
        }
        __syncthreads();

        // S = (scale*Q) @ K^T
        float s[4][4] = {};
        #pragma unroll
        for (int d = 0; d < HD; d++) {
            float4 a4 = *(const float4*)&sm.Qst[d][ty * 4];
            float4 b4 = *(const float4*)&sm.Kst[d][tx * 4];
            float av[4] = {a4.x, a4.y, a4.z, a4.w};
            float bv[4] = {b4.x, b4.y, b4.z, b4.w};
            #pragma unroll
            for (int i = 0; i < 4; i++)
                #pragma unroll
                for (int j = 0; j < 4; j++)
                    s[i][j] += av[i] * bv[j];
        }
        // additive mask (broadcast over queries)
        #pragma unroll
        for (int j = 0; j < 4; j++) {
            float mk = mask[t * 64 + tx * 4 + j];
            #pragma unroll
            for (int i = 0; i < 4; i++) s[i][j] += mk;
        }
        // row-max partials
        #pragma unroll
        for (int i = 0; i < 4; i++) {
            float mx = fmaxf(fmaxf(s[i][0], s[i][1]), fmaxf(s[i][2], s[i][3]));
            sm.red[ty * 4 + i][tx] = mx;
        }
        __syncthreads();
        if (tid < 64) {
            float mx = sm.red[tid][0];
            #pragma unroll
            for (int x = 1; x < 16; x++) mx = fmaxf(mx, sm.red[tid][x]);
            float mo = sm.m[tid];
            float mn = fmaxf(mo, mx);
            sm.alpha[tid] = __expf(mo - mn);
            sm.m[tid] = mn;
        }
        __syncthreads();
        // P = exp(S - m), row-sum partials, store P transposed
        #pragma unroll
        for (int i = 0; i < 4; i++) {
            float mr = sm.m[ty * 4 + i];
            float rs = 0.0f;
            #pragma unroll
            for (int j = 0; j < 4; j++) {
                float p = __expf(s[i][j] - mr);
                sm.Pst[tx * 4 + j][ty * 4 + i] = p;
                rs += p;
            }
            sm.red[ty * 4 + i][tx] = rs;
        }
        __syncthreads();
        if (tid < 64) {
            float su = 0.0f;
            #pragma unroll
            for (int x = 0; x < 16; x++) su += sm.red[tid][x];
            sm.l[tid] = sm.l[tid] * sm.alpha[tid] + su;
        }
        // O = O*alpha + P @ V
        #pragma unroll
        for (int i = 0; i < 4; i++) {
            float al = sm.alpha[ty * 4 + i];
            #pragma unroll
            for (int j = 0; j < 4; j++) o[i][j] *= al;
        }
        #pragma unroll
        for (int k = 0; k < 64; k++) {
            float4 vb = *(const float4*)&sm.Vs[k][tx * 4];
            float bv[4] = {vb.x, vb.y, vb.z, vb.w};
            float pv[4];
            #pragma unroll
            for (int i = 0; i < 4; i++) pv[i] = sm.Pst[k][ty * 4 + i];
            #pragma unroll
            for (int i = 0; i < 4; i++)
                #pragma unroll
                for (int j = 0; j < 4; j++)
                    o[i][j] += pv[i] * bv[j];
        }
    }
    __syncthreads();
    #pragma unroll
    for (int i = 0; i < 4; i++) {
        float inv = 1.0f / sm.l[ty * 4 + i];
        float4 ov;
        ov.x = o[i][0] * inv; ov.y = o[i][1] * inv;
        ov.z = o[i][2] * inv; ov.w = o[i][3] * inv;
        *(float4*)(Og + (size_t)(q0 + ty * 4 + i) * D + h * HD + tx * 4) = ov;
    }
}

// ----------------------------------------------------------------------------
extern "C" void kernel_launch(void* const* d_in, const int* in_sizes, int n_in,
                              void* d_out, int out_size)
{
    const float* hidden = (const float*)d_in[0];
    const float* enc    = (const float*)d_in[1];
    const float* mask   = (const float*)d_in[2];
    const float* qw  = (const float*)d_in[3];
    const float* qb  = (const float*)d_in[4];
    const float* kw  = (const float*)d_in[5];
    const float* kb  = (const float*)d_in[6];
    const float* vw  = (const float*)d_in[7];
    const float* vb  = (const float*)d_in[8];
    const float* nq  = (const float*)d_in[9];
    const float* nk  = (const float*)d_in[10];
    // d_in[11], d_in[12]: add_q_proj (dead — context output is discarded)
    const float* akw = (const float*)d_in[13];
    const float* akb = (const float*)d_in[14];
    const float* avw = (const float*)d_in[15];
    const float* avb = (const float*)d_in[16];
    // d_in[17]: norm_added_q (dead)
    const float* nak = (const float*)d_in[18];
    const float* ow  = (const float*)d_in[19];
    const float* ob  = (const float*)d_in[20];
    // d_in[21..24]: to_add_out (dead), attn_heads, attn_head_dim
    float* out = (float*)d_out;

    float *Q, *K, *V, *AO;
    cudaGetSymbolAddress((void**)&Q,  g_Q);
    cudaGetSymbolAddress((void**)&K,  g_K);
    cudaGetSymbolAddress((void**)&V,  g_V);
    cudaGetSymbolAddress((void**)&AO, g_AO);

    cudaFuncSetAttribute(flash_attn, cudaFuncAttributeMaxDynamicSharedMemorySize,
                         (int)sizeof(FlashSmem));

    dim3 blk(256);
    dim3 gHid(D / 64, S_HID / 64);
    dim3 gEnc(D / 64, S_ENC / 64);

    // Projections (add_q skipped — its output is discarded upstream)
    gemm_nt_bias<<<gHid, blk>>>(hidden, qw, qb, Q, S_HID, D, D);
    gemm_nt_bias<<<gHid, blk>>>(hidden, kw, kb, K, S_HID, D, D);
    gemm_nt_bias<<<gHid, blk>>>(hidden, vw, vb, V, S_HID, D, D);
    gemm_nt_bias<<<gEnc, blk>>>(enc, akw, akb, K + (size_t)S_HID * D, S_ENC, D, D);
    gemm_nt_bias<<<gEnc, blk>>>(enc, avw, avb, V + (size_t)S_HID * D, S_ENC, D, D);

    // Per-head RMSNorm (q on hidden only; k on both streams)
    rmsnorm_heads<<<(S_HID * NH) / 8, 256>>>(Q, nq, S_HID * NH);
    rmsnorm_heads<<<(S_HID * NH) / 8, 256>>>(K, nk, S_HID * NH);
    rmsnorm_heads<<<(S_ENC * NH) / 8, 256>>>(K + (size_t)S_HID * D, nak, S_ENC * NH);

    // Attention over T=2304 keys, only the 2048 hidden queries
    flash_attn<<<dim3(S_HID / 64, NH), blk, sizeof(FlashSmem)>>>(Q, K, V, mask, AO);

    // Output projection straight into d_out
    gemm_nt_bias<<<gHid, blk>>>(AO, ow, ob, out, S_HID, D, D);
}

// round 5
// speedup vs baseline: 5.6301x; 5.6301x over previous
#include <cuda_runtime.h>
#include <cuda_fp16.h>
#include <stdint.h>
#include <math.h>

typedef unsigned int u32;

#define MD    1536
#define SHID  2048
#define SENC  256
#define TTOT  2304
#define NHEAD 24
#define HDIM  64

// ---------------- scratch (__device__ globals: allocation-free rule) --------
__device__ __half g_h16 [SHID * MD];
__device__ __half g_e16 [SENC * MD];
__device__ __half g_w16 [6 * MD * MD];
__device__ float  g_Qf  [SHID * MD];
__device__ float  g_Kf  [TTOT * MD];
__device__ __half g_Q16 [SHID * MD];
__device__ __half g_K16 [TTOT * MD];
__device__ __half g_V16 [TTOT * MD];
__device__ __half g_AO16[SHID * MD];

// ---------------- small helpers --------------------------------------------
__device__ __forceinline__ void ldsm4(u32* r, u32 addr)
{
    asm volatile("ldmatrix.sync.aligned.m8n8.x4.shared.b16 {%0,%1,%2,%3}, [%4];"
                 : "=r"(r[0]), "=r"(r[1]), "=r"(r[2]), "=r"(r[3]) : "r"(addr));
}

__device__ __forceinline__ void ldsm4t(u32* r, u32 addr)
{
    asm volatile("ldmatrix.sync.aligned.m8n8.x4.trans.shared.b16 {%0,%1,%2,%3}, [%4];"
                 : "=r"(r[0]), "=r"(r[1]), "=r"(r[2]), "=r"(r[3]) : "r"(addr));
}

__device__ __forceinline__ void mma16816(float* c, const u32* a, u32 b0, u32 b1)
{
    asm volatile(
        "mma.sync.aligned.m16n8k16.row.col.f32.f16.f16.f32 "
        "{%0,%1,%2,%3}, {%4,%5,%6,%7}, {%8,%9}, {%0,%1,%2,%3};"
        : "+f"(c[0]), "+f"(c[1]), "+f"(c[2]), "+f"(c[3])
        : "r"(a[0]), "r"(a[1]), "r"(a[2]), "r"(a[3]), "r"(b0), "r"(b1));
}

__device__ __forceinline__ u32 packh2(float x, float y)
{
    __half2 h = __floats2half2_rn(x, y);
    return *reinterpret_cast<u32*>(&h);
}

// ---------------- fp32 -> fp16 convert --------------------------------------
__global__ __launch_bounds__(256) void cvt_f32_f16(
    const float* __restrict__ src, __half* __restrict__ dst, int n4)
{
    int i = blockIdx.x * 256 + threadIdx.x;
    if (i >= n4) return;
    float4 v = ((const float4*)src)[i];
    ((__half2*)dst)[2 * i + 0] = __floats2half2_rn(v.x, v.y);
    ((__half2*)dst)[2 * i + 1] = __floats2half2_rn(v.z, v.w);
}

// ---------------- fp16 tensor-core GEMM: C = A[M,K] @ W[N,K]^T + bias -------
// BM=128, BN=64, BK=32, 256 threads (8 warps = 2 x 4), warp tile 64x16.
// out_half != 0 writes __half, else float.
__global__ __launch_bounds__(256) void gemm_f16(
    const __half* __restrict__ A, const __half* __restrict__ W,
    const float* __restrict__ bias, void* __restrict__ Cout,
    int M, int N, int K, int out_half)
{
    __shared__ __align__(16) __half As[128][40];
    __shared__ __align__(16) __half Bs[64][40];
    const int bm = blockIdx.y * 128;
    const int bn = blockIdx.x * 64;
    const int tid  = threadIdx.x;
    const int lane = tid & 31;
    const int warp = tid >> 5;
    const int wm  = warp & 1;
    const int wn  = warp >> 1;
    const int oct = lane >> 3;
    const int oj  = lane & 7;

    const u32 sA = (u32)__cvta_generic_to_shared(&As[0][0]);
    const u32 sB = (u32)__cvta_generic_to_shared(&Bs[0][0]);

    float acc[8][4];
    #pragma unroll
    for (int q = 0; q < 8; q++)
    {
        #pragma unroll
        for (int x = 0; x < 4; x++) acc[q][x] = 0.0f;
    }

    const int lr = tid >> 2;          // 0..63
    const int lc = (tid & 3) * 8;     // halves within 32

    for (int k0 = 0; k0 < K; k0 += 32)
    {
        *(int4*)&As[lr][lc]      = *(const int4*)(A + (size_t)(bm + lr) * K + k0 + lc);
        *(int4*)&As[lr + 64][lc] = *(const int4*)(A + (size_t)(bm + lr + 64) * K + k0 + lc);
        *(int4*)&Bs[lr][lc]      = *(const int4*)(W + (size_t)(bn + lr) * K + k0 + lc);
        __syncthreads();

        #pragma unroll
        for (int ks = 0; ks < 2; ks++)
        {
            const int ksh = ks * 16;
            u32 af[4][4];
            #pragma unroll
            for (int mi = 0; mi < 4; mi++)
            {
                int row = wm * 64 + mi * 16 + (oct & 1) * 8 + oj;
                int col = ksh + (oct >> 1) * 8;
                ldsm4(af[mi], sA + (u32)(row * 40 + col) * 2u);
            }
            u32 bf[4];
            {
                int row = wn * 16 + (oct >> 1) * 8 + oj;
                int col = ksh + (oct & 1) * 8;
                ldsm4(bf, sB + (u32)(row * 40 + col) * 2u);
            }
            #pragma unroll
            for (int mi = 0; mi < 4; mi++)
            {
                mma16816(acc[2 * mi + 0], af[mi], bf[0], bf[1]);
                mma16816(acc[2 * mi + 1], af[mi], bf[2], bf[3]);
            }
        }
        __syncthreads();
    }

    #pragma unroll
    for (int mi = 0; mi < 4; mi++)
    {
        #pragma unroll
        for (int ni = 0; ni < 2; ni++)
        {
            const float* c = acc[2 * mi + ni];
            int row = bm + wm * 64 + mi * 16 + (lane >> 2);
            int col = bn + wn * 16 + ni * 8 + (lane & 3) * 2;
            float b0 = bias[col];
            float b1 = bias[col + 1];
            if (out_half)
            {
                __half* C = (__half*)Cout;
                *(__half2*)(C + (size_t)row * N + col) =
                    __floats2half2_rn(c[0] + b0, c[1] + b1);
                *(__half2*)(C + (size_t)(row + 8) * N + col) =
                    __floats2half2_rn(c[2] + b0, c[3] + b1);
            }
            else
            {
                float* C = (float*)Cout;
                *(float2*)(C + (size_t)row * N + col) = make_float2(c[0] + b0, c[1] + b1);
                *(float2*)(C + (size_t)(row + 8) * N + col) = make_float2(c[2] + b0, c[3] + b1);
            }
        }
    }
}

// ---------------- per-head RMSNorm fp32 -> fp16 (extra scale folded) --------
__global__ __launch_bounds__(256) void rmsnorm_f32_f16(
    const float* __restrict__ X, const float* __restrict__ w,
    __half* __restrict__ Y, int ntasks, float outscale)
{
    int task = (blockIdx.x * blockDim.x + threadIdx.x) >> 5;
    int lane = threadIdx.x & 31;
    if (task >= ntasks) return;
    int row = task / NHEAD;
    int h   = task % NHEAD;
    const float* p = X + (size_t)row * MD + h * HDIM;
    float2 v = ((const float2*)p)[lane];
    float ss = v.x * v.x + v.y * v.y;
    #pragma unroll
    for (int o = 16; o; o >>= 1) ss += __shfl_xor_sync(0xffffffffu, ss, o);
    float r = rsqrtf(ss * (1.0f / HDIM) + 1e-6f) * outscale;
    __half2* q = (__half2*)(Y + (size_t)row * MD + h * HDIM);
    q[lane] = __floats2half2_rn(v.x * r * w[2 * lane], v.y * r * w[2 * lane + 1]);
}

// ---------------- fp16 flash attention (tensor core) ------------------------
// 128 threads = 4 warps; q-tile 64 (16 rows/warp), kv-tile 64, d=64.
// Q pre-scaled by 1/sqrt(HDIM). Output fp16.
__global__ __launch_bounds__(128) void flash16(
    const __half* __restrict__ Qg, const __half* __restrict__ Kg,
    const __half* __restrict__ Vg, const float* __restrict__ mask,
    __half* __restrict__ AO)
{
    __shared__ __align__(16) __half Qs[64][72];
    __shared__ __align__(16) __half Ks[64][72];
    __shared__ __align__(16) __half Vs[64][72];
    __shared__ float smask[64];
    const int h  = blockIdx.y;
    const int bq = blockIdx.x * 64;
    const int tid  = threadIdx.x;
    const int lane = tid & 31;
    const int warp = tid >> 5;
    const int oct = lane >> 3;
    const int oj  = lane & 7;
    const int cb  = (lane & 3) * 2;

    const u32 sQ = (u32)__cvta_generic_to_shared(&Qs[0][0]);
    const u32 sK = (u32)__cvta_generic_to_shared(&Ks[0][0]);
    const u32 sV = (u32)__cvta_generic_to_shared(&Vs[0][0]);

    #pragma unroll
    for (int l = 0; l < 4; l++)
    {
        int idx = tid + l * 128;
        int r  = idx >> 3;
        int cc = (idx & 7) * 8;
        *(int4*)&Qs[r][cc] = *(const int4*)(Qg + (size_t)(bq + r) * MD + h * HDIM + cc);
    }
    __syncthreads();
    u32 qa[4][4];
    #pragma unroll
    for (int kf = 0; kf < 4; kf++)
    {
        int row = warp * 16 + (oct & 1) * 8 + oj;
        int col = kf * 16 + (oct >> 1) * 8;
        ldsm4(qa[kf], sQ + (u32)(row * 72 + col) * 2u);
    }

    float m0 = -1e30f;
    float m1 = -1e30f;
    float l0 = 0.0f;
    float l1 = 0.0f;
    float oacc[8][4];
    #pragma unroll
    for (int dt = 0; dt < 8; dt++)
    {
        #pragma unroll
        for (int x = 0; x < 4; x++) oacc[dt][x] = 0.0f;
    }

    for (int t = 0; t < TTOT / 64; t++)
    {
        __syncthreads();
        #pragma unroll
        for (int l = 0; l < 4; l++)
        {
            int idx = tid + l * 128;
            int r  = idx >> 3;
            int cc = (idx & 7) * 8;
            *(int4*)&Ks[r][cc] = *(const int4*)(Kg + (size_t)(t * 64 + r) * MD + h * HDIM + cc);
            *(int4*)&Vs[r][cc] = *(const int4*)(Vg + (size_t)(t * 64 + r) * MD + h * HDIM + cc);
        }
        if (tid < 64) smask[tid] = mask[t * 64 + tid];
        __syncthreads();

        // S = Q @ K^T
        float s[8][4];
        #pragma unroll
        for (int jt = 0; jt < 8; jt++)
        {
            #pragma unroll
            for (int x = 0; x < 4; x++) s[jt][x] = 0.0f;
        }
        #pragma unroll
        for (int nb = 0; nb < 4; nb++)
        {
            #pragma unroll
            for (int kf = 0; kf < 4; kf++)
            {
                u32 bf[4];
                int row = nb * 16 + (oct >> 1) * 8 + oj;
                int col = kf * 16 + (oct & 1) * 8;
                ldsm4(bf, sK + (u32)(row * 72 + col) * 2u);
                mma16816(s[2 * nb + 0], qa[kf], bf[0], bf[1]);
                mma16816(s[2 * nb + 1], qa[kf], bf[2], bf[3]);
            }
        }

        // mask + online softmax
        float mx0 = -1e30f;
        float mx1 = -1e30f;
        #pragma unroll
        for (int jt = 0; jt < 8; jt++)
        {
            float mk0 = smask[jt * 8 + cb];
            float mk1 = smask[jt * 8 + cb + 1];
            s[jt][0] += mk0;
            s[jt][1] += mk1;
            s[jt][2] += mk0;
            s[jt][3] += mk1;
            mx0 = fmaxf(mx0, fmaxf(s[jt][0], s[jt][1]));
            mx1 = fmaxf(mx1, fmaxf(s[jt][2], s[jt][3]));
        }
        mx0 = fmaxf(mx0, __shfl_xor_sync(0xffffffffu, mx0, 1));
        mx0 = fmaxf(mx0, __shfl_xor_sync(0xffffffffu, mx0, 2));
        mx1 = fmaxf(mx1, __shfl_xor_sync(0xffffffffu, mx1, 1));
        mx1 = fmaxf(mx1, __shfl_xor_sync(0xffffffffu, mx1, 2));
        float mn0 = fmaxf(m0, mx0);
        float a0  = __expf(m0 - mn0);
        m0 = mn0;
        float mn1 = fmaxf(m1, mx1);
        float a1  = __expf(m1 - mn1);
        m1 = mn1;

        float rs0 = 0.0f;
        float rs1 = 0.0f;
        #pragma unroll
        for (int jt = 0; jt < 8; jt++)
        {
            s[jt][0] = __expf(s[jt][0] - m0); rs0 += s[jt][0];
            s[jt][1] = __expf(s[jt][1] - m0); rs0 += s[jt][1];
            s[jt][2] = __expf(s[jt][2] - m1); rs1 += s[jt][2];
            s[jt][3] = __expf(s[jt][3] - m1); rs1 += s[jt][3];
        }
        l0 = l0 * a0 + rs0;
        l1 = l1 * a1 + rs1;

        // P fragments (A operand for P@V)
        u32 pa[4][4];
        #pragma unroll
        for (int kf = 0; kf < 4; kf++)
        {
            pa[kf][0] = packh2(s[2 * kf + 0][0], s[2 * kf + 0][1]);
            pa[kf][1] = packh2(s[2 * kf + 0][2], s[2 * kf + 0][3]);
            pa[kf][2] = packh2(s[2 * kf + 1][0], s[2 * kf + 1][1]);
            pa[kf][3] = packh2(s[2 * kf + 1][2], s[2 * kf + 1][3]);
        }
        #pragma unroll
        for (int dt = 0; dt < 8; dt++)
        {
            oacc[dt][0] *= a0;
            oacc[dt][1] *= a0;
            oacc[dt][2] *= a1;
            oacc[dt][3] *= a1;
        }
        // O += P @ V (B via ldmatrix.trans on Vs[kv][d])
        #pragma unroll
        for (int db = 0; db < 4; db++)
        {
            #pragma unroll
            for (int kf = 0; kf < 4; kf++)
            {
                u32 bf[4];
                int row = kf * 16 + (oct & 1) * 8 + oj;
                int col = db * 16 + (oct >> 1) * 8;
                ldsm4t(bf, sV + (u32)(row * 72 + col) * 2u);
                mma16816(oacc[2 * db + 0], pa[kf], bf[0], bf[1]);
                mma16816(oacc[2 * db + 1], pa[kf], bf[2], bf[3]);
            }
        }
    }

    l0 += __shfl_xor_sync(0xffffffffu, l0, 1);
    l0 += __shfl_xor_sync(0xffffffffu, l0, 2);
    l1 += __shfl_xor_sync(0xffffffffu, l1, 1);
    l1 += __shfl_xor_sync(0xffffffffu, l1, 2);
    float inv0 = 1.0f / l0;
    float inv1 = 1.0f / l1;

    #pragma unroll
    for (int dt = 0; dt < 8; dt++)
    {
        int row = bq + warp * 16 + (lane >> 2);
        int col = h * HDIM + dt * 8 + cb;
        *(__half2*)(AO + (size_t)row * MD + col) =
            __floats2half2_rn(oacc[dt][0] * inv0, oacc[dt][1] * inv0);
        *(__half2*)(AO + (size_t)(row + 8) * MD + col) =
            __floats2half2_rn(oacc[dt][2] * inv1, oacc[dt][3] * inv1);
    }
}

// ----------------------------------------------------------------------------
extern "C" void kernel_launch(void* const* d_in, const int* in_sizes, int n_in,
                              void* d_out, int out_size)
{
    const float* hidden = (const float*)d_in[0];
    const float* enc    = (const float*)d_in[1];
    const float* mask   = (const float*)d_in[2];
    const float* qw  = (const float*)d_in[3];
    const float* qb  = (const float*)d_in[4];
    const float* kw  = (const float*)d_in[5];
    const float* kb  = (const float*)d_in[6];
    const float* vw  = (const float*)d_in[7];
    const float* vb  = (const float*)d_in[8];
    const float* nq  = (const float*)d_in[9];
    const float* nk  = (const float*)d_in[10];
    const float* akw = (const float*)d_in[13];
    const float* akb = (const float*)d_in[14];
    const float* avw = (const float*)d_in[15];
    const float* avb = (const float*)d_in[16];
    const float* nak = (const float*)d_in[18];
    const float* ow  = (const float*)d_in[19];
    const float* ob  = (const float*)d_in[20];
    float* outp = (float*)d_out;

    __half* h16 = 0;
    __half* e16 = 0;
    __half* w16 = 0;
    __half* Q16 = 0;
    __half* K16 = 0;
    __half* V16 = 0;
    __half* AO16 = 0;
    float* Qf = 0;
    float* Kf = 0;
    cudaGetSymbolAddress((void**)&h16,  g_h16);
    cudaGetSymbolAddress((void**)&e16,  g_e16);
    cudaGetSymbolAddress((void**)&w16,  g_w16);
    cudaGetSymbolAddress((void**)&Qf,   g_Qf);
    cudaGetSymbolAddress((void**)&Kf,   g_Kf);
    cudaGetSymbolAddress((void**)&Q16,  g_Q16);
    cudaGetSymbolAddress((void**)&K16,  g_K16);
    cudaGetSymbolAddress((void**)&V16,  g_V16);
    cudaGetSymbolAddress((void**)&AO16, g_AO16);

    __half* wq16  = w16 + 0 * (size_t)MD * MD;
    __half* wk16  = w16 + 1 * (size_t)MD * MD;
    __half* wv16  = w16 + 2 * (size_t)MD * MD;
    __half* wak16 = w16 + 3 * (size_t)MD * MD;
    __half* wav16 = w16 + 4 * (size_t)MD * MD;
    __half* wo16  = w16 + 5 * (size_t)MD * MD;

    const int nw4 = MD * MD / 4;
    const int nh4 = SHID * MD / 4;
    const int ne4 = SENC * MD / 4;
    dim3 cblk(256, 1, 1);
    dim3 gw((nw4 + 255) / 256, 1, 1);
    dim3 gh((nh4 + 255) / 256, 1, 1);
    dim3 ge((ne4 + 255) / 256, 1, 1);
    cvt_f32_f16<<<gh, cblk>>>(hidden, h16, nh4);
    cvt_f32_f16<<<ge, cblk>>>(enc, e16, ne4);
    cvt_f32_f16<<<gw, cblk>>>(qw,  wq16,  nw4);
    cvt_f32_f16<<<gw, cblk>>>(kw,  wk16,  nw4);
    cvt_f32_f16<<<gw, cblk>>>(vw,  wv16,  nw4);
    cvt_f32_f16<<<gw, cblk>>>(akw, wak16, nw4);
    cvt_f32_f16<<<gw, cblk>>>(avw, wav16, nw4);
    cvt_f32_f16<<<gw, cblk>>>(ow,  wo16,  nw4);

    dim3 blk(256, 1, 1);
    dim3 gHid(MD / 64, SHID / 128, 1);
    dim3 gEnc(MD / 64, SENC / 128, 1);

    gemm_f16<<<gHid, blk>>>(h16, wq16, qb, Qf, SHID, MD, MD, 0);
    gemm_f16<<<gHid, blk>>>(h16, wk16, kb, Kf, SHID, MD, MD, 0);
    gemm_f16<<<gHid, blk>>>(h16, wv16, vb, V16, SHID, MD, MD, 1);
    gemm_f16<<<gEnc, blk>>>(e16, wak16, akb, Kf + (size_t)SHID * MD, SENC, MD, MD, 0);
    gemm_f16<<<gEnc, blk>>>(e16, wav16, avb, V16 + (size_t)SHID * MD, SENC, MD, MD, 1);

    // Q gets the 1/sqrt(HDIM)=0.125 attention scale folded in.
    dim3 rblk(256, 1, 1);
    dim3 gr1((SHID * NHEAD) / 8, 1, 1);
    dim3 gr2((SENC * NHEAD) / 8, 1, 1);
    rmsnorm_f32_f16<<<gr1, rblk>>>(Qf, nq, Q16, SHID * NHEAD, 0.125f);
    rmsnorm_f32_f16<<<gr1, rblk>>>(Kf, nk, K16, SHID * NHEAD, 1.0f);
    rmsnorm_f32_f16<<<gr2, rblk>>>(Kf + (size_t)SHID * MD, nak,
                                   K16 + (size_t)SHID * MD, SENC * NHEAD, 1.0f);

    dim3 gF(SHID / 64, NHEAD, 1);
    dim3 fblk(128, 1, 1);
    flash16<<<gF, fblk>>>(Q16, K16, V16, mask, AO16);

    gemm_f16<<<gHid, blk>>>(AO16, wo16, ob, outp, SHID, MD, MD, 0);
}

// round 6
// speedup vs baseline: 5.8551x; 1.0400x over previous
#include <cuda_runtime.h>
#include <cuda_fp16.h>
#include <stdint.h>
#include <math.h>

typedef unsigned int u32;

#define MD    1536
#define SHID  2048
#define SENC  256
#define TTOT  2304
#define NHEAD 24
#define HDIM  64

// ---------------- scratch (__device__ globals: allocation-free rule) --------
__device__ __half g_h16 [SHID * MD];
__device__ __half g_e16 [SENC * MD];
__device__ __half g_w16 [6 * MD * MD];
__device__ float  g_Qf  [SHID * MD];
__device__ float  g_Kf  [TTOT * MD];
__device__ __half g_Q16 [SHID * MD];
__device__ __half g_K16 [TTOT * MD];
__device__ __half g_V16 [TTOT * MD];
__device__ __half g_AO16[SHID * MD];

// ---------------- small helpers --------------------------------------------
__device__ __forceinline__ void ldsm4(u32* r, u32 addr)
{
    asm volatile("ldmatrix.sync.aligned.m8n8.x4.shared.b16 {%0,%1,%2,%3}, [%4];"
                 : "=r"(r[0]), "=r"(r[1]), "=r"(r[2]), "=r"(r[3]) : "r"(addr));
}

__device__ __forceinline__ void ldsm4t(u32* r, u32 addr)
{
    asm volatile("ldmatrix.sync.aligned.m8n8.x4.trans.shared.b16 {%0,%1,%2,%3}, [%4];"
                 : "=r"(r[0]), "=r"(r[1]), "=r"(r[2]), "=r"(r[3]) : "r"(addr));
}

__device__ __forceinline__ void mma16816(float* c, const u32* a, u32 b0, u32 b1)
{
    asm volatile(
        "mma.sync.aligned.m16n8k16.row.col.f32.f16.f16.f32 "
        "{%0,%1,%2,%3}, {%4,%5,%6,%7}, {%8,%9}, {%0,%1,%2,%3};"
        : "+f"(c[0]), "+f"(c[1]), "+f"(c[2]), "+f"(c[3])
        : "r"(a[0]), "r"(a[1]), "r"(a[2]), "r"(a[3]), "r"(b0), "r"(b1));
}

__device__ __forceinline__ u32 packh2(float x, float y)
{
    __half2 h = __floats2half2_rn(x, y);
    return *reinterpret_cast<u32*>(&h);
}

__device__ __forceinline__ void cp16(u32 smem_dst, const void* gmem_src)
{
    asm volatile("cp.async.cg.shared.global [%0], [%1], 16;"
                 :: "r"(smem_dst), "l"(gmem_src));
}

__device__ __forceinline__ void cp_commit()
{
    asm volatile("cp.async.commit_group;");
}

__device__ __forceinline__ void cp_wait1()
{
    asm volatile("cp.async.wait_group 1;");
}

__device__ __forceinline__ void cp_wait0()
{
    asm volatile("cp.async.wait_group 0;");
}

// ---------------- merged fp32 -> fp16 convert (one launch, 8 segments) -----
struct CvtJobs
{
    const float* src[8];
    __half*      dst[8];
    int          n4[8];
};

__global__ __launch_bounds__(256) void cvt_multi(CvtJobs jobs)
{
    int seg = blockIdx.y;
    const float* __restrict__ src = jobs.src[seg];
    __half* __restrict__ dst = jobs.dst[seg];
    int n4 = jobs.n4[seg];
    int i = blockIdx.x * 256 + threadIdx.x;
    if (i >= n4) return;
    float4 v = ((const float4*)src)[i];
    ((__half2*)dst)[2 * i + 0] = __floats2half2_rn(v.x, v.y);
    ((__half2*)dst)[2 * i + 1] = __floats2half2_rn(v.z, v.w);
}

// ---------------- fp16 tensor-core GEMM v2: C = A[M,K] @ W[N,K]^T + bias ----
// BM=128, BN=128, BK=32, 256 threads (8 warps: 2 m x 4 n), warp tile 64x32.
// 2-stage cp.async double buffer. out_half != 0 writes __half, else float.
__global__ __launch_bounds__(256) void gemm_f16(
    const __half* __restrict__ A, const __half* __restrict__ W,
    const float* __restrict__ bias, void* __restrict__ Cout,
    int M, int N, int K, int out_half)
{
    __shared__ __align__(16) __half As[2][128][40];
    __shared__ __align__(16) __half Bs[2][128][40];
    const int bm = blockIdx.y * 128;
    const int bn = blockIdx.x * 128;
    const int tid  = threadIdx.x;
    const int lane = tid & 31;
    const int warp = tid >> 5;
    const int wm  = warp & 1;        // 2 warp-rows of 64
    const int wn  = warp >> 1;       // 4 warp-cols of 32
    const int oct = lane >> 3;
    const int oj  = lane & 7;

    const u32 sA = (u32)__cvta_generic_to_shared(&As[0][0][0]);
    const u32 sB = (u32)__cvta_generic_to_shared(&Bs[0][0][0]);
    const u32 stageBytes = 128 * 40 * 2;

    float acc[4][4][4];
    #pragma unroll
    for (int mi = 0; mi < 4; mi++)
        #pragma unroll
        for (int ni = 0; ni < 4; ni++)
            #pragma unroll
            for (int x = 0; x < 4; x++) acc[mi][ni][x] = 0.0f;

    const int lr = tid >> 2;          // 0..63
    const int lc = (tid & 3) * 8;     // halves within 32

    const int KT = K >> 5;            // BK=32 steps

    // stage-load macro logic
    // A rows bm+lr, bm+lr+64; B rows bn+lr, bn+lr+64
    {
        const int k0 = 0;
        u32 dA = sA + (u32)(lr * 40 + lc) * 2u;
        cp16(dA, A + (size_t)(bm + lr) * K + k0 + lc);
        cp16(dA + 64u * 80u, A + (size_t)(bm + lr + 64) * K + k0 + lc);
        u32 dB = sB + (u32)(lr * 40 + lc) * 2u;
        cp16(dB, W + (size_t)(bn + lr) * K + k0 + lc);
        cp16(dB + 64u * 80u, W + (size_t)(bn + lr + 64) * K + k0 + lc);
        cp_commit();
    }

    for (int kt = 0; kt < KT; kt++)
    {
        if (kt + 1 < KT)
        {
            const int k0 = (kt + 1) << 5;
            const u32 so = ((kt + 1) & 1) ? stageBytes : 0u;
            u32 dA = sA + so + (u32)(lr * 40 + lc) * 2u;
            cp16(dA, A + (size_t)(bm + lr) * K + k0 + lc);
            cp16(dA + 64u * 80u, A + (size_t)(bm + lr + 64) * K + k0 + lc);
            u32 dB = sB + so + (u32)(lr * 40 + lc) * 2u;
            cp16(dB, W + (size_t)(bn + lr) * K + k0 + lc);
            cp16(dB + 64u * 80u, W + (size_t)(bn + lr + 64) * K + k0 + lc);
            cp_commit();
            cp_wait1();
        }
        else
        {
            cp_wait0();
        }
        __syncthreads();

        const u32 so = (kt & 1) ? stageBytes : 0u;
        #pragma unroll
        for (int ks = 0; ks < 2; ks++)
        {
            const int ksh = ks * 16;
            u32 af[4][4];
            #pragma unroll
            for (int mi = 0; mi < 4; mi++)
            {
                int row = wm * 64 + mi * 16 + (oct & 1) * 8 + oj;
                int col = ksh + (oct >> 1) * 8;
                ldsm4(af[mi], sA + so + (u32)(row * 40 + col) * 2u);
            }
            u32 bf[2][4];
            #pragma unroll
            for (int nb = 0; nb < 2; nb++)
            {
                int row = wn * 32 + nb * 16 + (oct >> 1) * 8 + oj;
                int col = ksh + (oct & 1) * 8;
                ldsm4(bf[nb], sB + so + (u32)(row * 40 + col) * 2u);
            }
            #pragma unroll
            for (int mi = 0; mi < 4; mi++)
            {
                #pragma unroll
                for (int nb = 0; nb < 2; nb++)
                {
                    mma16816(acc[mi][2 * nb + 0], af[mi], bf[nb][0], bf[nb][1]);
                    mma16816(acc[mi][2 * nb + 1], af[mi], bf[nb][2], bf[nb][3]);
                }
            }
        }
        __syncthreads();
    }

    #pragma unroll
    for (int mi = 0; mi < 4; mi++)
    {
        #pragma unroll
        for (int ni = 0; ni < 4; ni++)
        {
            const float* c = acc[mi][ni];
            int row = bm + wm * 64 + mi * 16 + (lane >> 2);
            int col = bn + wn * 32 + ni * 8 + (lane & 3) * 2;
            float b0 = bias[col];
            float b1 = bias[col + 1];
            if (out_half)
            {
                __half* C = (__half*)Cout;
                *(__half2*)(C + (size_t)row * N + col) =
                    __floats2half2_rn(c[0] + b0, c[1] + b1);
                *(__half2*)(C + (size_t)(row + 8) * N + col) =
                    __floats2half2_rn(c[2] + b0, c[3] + b1);
            }
            else
            {
                float* C = (float*)Cout;
                *(float2*)(C + (size_t)row * N + col) = make_float2(c[0] + b0, c[1] + b1);
                *(float2*)(C + (size_t)(row + 8) * N + col) = make_float2(c[2] + b0, c[3] + b1);
            }
        }
    }
}

// ---------------- per-head RMSNorm fp32 -> fp16 (extra scale folded) --------
__global__ __launch_bounds__(256) void rmsnorm_f32_f16(
    const float* __restrict__ X, const float* __restrict__ w,
    __half* __restrict__ Y, int ntasks, float outscale)
{
    int task = (blockIdx.x * blockDim.x + threadIdx.x) >> 5;
    int lane = threadIdx.x & 31;
    if (task >= ntasks) return;
    int row = task / NHEAD;
    int h   = task % NHEAD;
    const float* p = X + (size_t)row * MD + h * HDIM;
    float2 v = ((const float2*)p)[lane];
    float ss = v.x * v.x + v.y * v.y;
    #pragma unroll
    for (int o = 16; o; o >>= 1) ss += __shfl_xor_sync(0xffffffffu, ss, o);
    float r = rsqrtf(ss * (1.0f / HDIM) + 1e-6f) * outscale;
    __half2* q = (__half2*)(Y + (size_t)row * MD + h * HDIM);
    q[lane] = __floats2half2_rn(v.x * r * w[2 * lane], v.y * r * w[2 * lane + 1]);
}

// ---------------- fp16 flash attention (tensor core) ------------------------
// 256 threads = 8 warps; q-tile 128 (16 rows/warp), kv-tile 64, d=64.
// Q pre-scaled by 1/sqrt(HDIM). Output fp16.
__global__ __launch_bounds__(256) void flash16(
    const __half* __restrict__ Qg, const __half* __restrict__ Kg,
    const __half* __restrict__ Vg, const float* __restrict__ mask,
    __half* __restrict__ AO)
{
    __shared__ __align__(16) __half Qs[128][72];
    __shared__ __align__(16) __half Ks[64][72];
    __shared__ __align__(16) __half Vs[64][72];
    __shared__ float smask[64];
    const int h  = blockIdx.y;
    const int bq = blockIdx.x * 128;
    const int tid  = threadIdx.x;
    const int lane = tid & 31;
    const int warp = tid >> 5;
    const int oct = lane >> 3;
    const int oj  = lane & 7;
    const int cb  = (lane & 3) * 2;

    const u32 sQ = (u32)__cvta_generic_to_shared(&Qs[0][0]);
    const u32 sK = (u32)__cvta_generic_to_shared(&Ks[0][0]);
    const u32 sV = (u32)__cvta_generic_to_shared(&Vs[0][0]);

    #pragma unroll
    for (int l = 0; l < 4; l++)
    {
        int idx = tid + l * 256;
        int r  = idx >> 3;
        int cc = (idx & 7) * 8;
        *(int4*)&Qs[r][cc] = *(const int4*)(Qg + (size_t)(bq + r) * MD + h * HDIM + cc);
    }
    __syncthreads();
    u32 qa[4][4];
    #pragma unroll
    for (int kf = 0; kf < 4; kf++)
    {
        int row = warp * 16 + (oct & 1) * 8 + oj;
        int col = kf * 16 + (oct >> 1) * 8;
        ldsm4(qa[kf], sQ + (u32)(row * 72 + col) * 2u);
    }

    float m0 = -1e30f;
    float m1 = -1e30f;
    float l0 = 0.0f;
    float l1 = 0.0f;
    float oacc[8][4];
    #pragma unroll
    for (int dt = 0; dt < 8; dt++)
    {
        #pragma unroll
        for (int x = 0; x < 4; x++) oacc[dt][x] = 0.0f;
    }

    for (int t = 0; t < TTOT / 64; t++)
    {
        __syncthreads();
        #pragma unroll
        for (int l = 0; l < 2; l++)
        {
            int idx = tid + l * 256;
            int r  = idx >> 3;
            int cc = (idx & 7) * 8;
            *(int4*)&Ks[r][cc] = *(const int4*)(Kg + (size_t)(t * 64 + r) * MD + h * HDIM + cc);
            *(int4*)&Vs[r][cc] = *(const int4*)(Vg + (size_t)(t * 64 + r) * MD + h * HDIM + cc);
        }
        if (tid < 64) smask[tid] = mask[t * 64 + tid];
        __syncthreads();

        // S = Q @ K^T
        float s[8][4];
        #pragma unroll
        for (int jt = 0; jt < 8; jt++)
        {
            #pragma unroll
            for (int x = 0; x < 4; x++) s[jt][x] = 0.0f;
        }
        #pragma unroll
        for (int nb = 0; nb < 4; nb++)
        {
            #pragma unroll
            for (int kf = 0; kf < 4; kf++)
            {
                u32 bf[4];
                int row = nb * 16 + (oct >> 1) * 8 + oj;
                int col = kf * 16 + (oct & 1) * 8;
                ldsm4(bf, sK + (u32)(row * 72 + col) * 2u);
                mma16816(s[2 * nb + 0], qa[kf], bf[0], bf[1]);
                mma16816(s[2 * nb + 1], qa[kf], bf[2], bf[3]);
            }
        }

        // mask + online softmax
        float mx0 = -1e30f;
        float mx1 = -1e30f;
        #pragma unroll
        for (int jt = 0; jt < 8; jt++)
        {
            float mk0 = smask[jt * 8 + cb];
            float mk1 = smask[jt * 8 + cb + 1];
            s[jt][0] += mk0;
            s[jt][1] += mk1;
            s[jt][2] += mk0;
            s[jt][3] += mk1;
            mx0 = fmaxf(mx0, fmaxf(s[jt][0], s[jt][1]));
            mx1 = fmaxf(mx1, fmaxf(s[jt][2], s[jt][3]));
        }
        mx0 = fmaxf(mx0, __shfl_xor_sync(0xffffffffu, mx0, 1));
        mx0 = fmaxf(mx0, __shfl_xor_sync(0xffffffffu, mx0, 2));
        mx1 = fmaxf(mx1, __shfl_xor_sync(0xffffffffu, mx1, 1));
        mx1 = fmaxf(mx1, __shfl_xor_sync(0xffffffffu, mx1, 2));
        float mn0 = fmaxf(m0, mx0);
        float a0  = __expf(m0 - mn0);
        m0 = mn0;
        float mn1 = fmaxf(m1, mx1);
        float a1  = __expf(m1 - mn1);
        m1 = mn1;

        float rs0 = 0.0f;
        float rs1 = 0.0f;
        #pragma unroll
        for (int jt = 0; jt < 8; jt++)
        {
            s[jt][0] = __expf(s[jt][0] - m0); rs0 += s[jt][0];
            s[jt][1] = __expf(s[jt][1] - m0); rs0 += s[jt][1];
            s[jt][2] = __expf(s[jt][2] - m1); rs1 += s[jt][2];
            s[jt][3] = __expf(s[jt][3] - m1); rs1 += s[jt][3];
        }
        l0 = l0 * a0 + rs0;
        l1 = l1 * a1 + rs1;

        // P fragments (A operand for P@V)
        u32 pa[4][4];
        #pragma unroll
        for (int kf = 0; kf < 4; kf++)
        {
            pa[kf][0] = packh2(s[2 * kf + 0][0], s[2 * kf + 0][1]);
            pa[kf][1] = packh2(s[2 * kf + 0][2], s[2 * kf + 0][3]);
            pa[kf][2] = packh2(s[2 * kf + 1][0], s[2 * kf + 1][1]);
            pa[kf][3] = packh2(s[2 * kf + 1][2], s[2 * kf + 1][3]);
        }
        #pragma unroll
        for (int dt = 0; dt < 8; dt++)
        {
            oacc[dt][0] *= a0;
            oacc[dt][1] *= a0;
            oacc[dt][2] *= a1;
            oacc[dt][3] *= a1;
        }
        // O += P @ V (B via ldmatrix.trans on Vs[kv][d])
        #pragma unroll
        for (int db = 0; db < 4; db++)
        {
            #pragma unroll
            for (int kf = 0; kf < 4; kf++)
            {
                u32 bf[4];
                int row = kf * 16 + (oct & 1) * 8 + oj;
                int col = db * 16 + (oct >> 1) * 8;
                ldsm4t(bf, sV + (u32)(row * 72 + col) * 2u);
                mma16816(oacc[2 * db + 0], pa[kf], bf[0], bf[1]);
                mma16816(oacc[2 * db + 1], pa[kf], bf[2], bf[3]);
            }
        }
    }

    l0 += __shfl_xor_sync(0xffffffffu, l0, 1);
    l0 += __shfl_xor_sync(0xffffffffu, l0, 2);
    l1 += __shfl_xor_sync(0xffffffffu, l1, 1);
    l1 += __shfl_xor_sync(0xffffffffu, l1, 2);
    float inv0 = 1.0f / l0;
    float inv1 = 1.0f / l1;

    #pragma unroll
    for (int dt = 0; dt < 8; dt++)
    {
        int row = bq + warp * 16 + (lane >> 2);
        int col = h * HDIM + dt * 8 + cb;
        *(__half2*)(AO + (size_t)row * MD + col) =
            __floats2half2_rn(oacc[dt][0] * inv0, oacc[dt][1] * inv0);
        *(__half2*)(AO + (size_t)(row + 8) * MD + col) =
            __floats2half2_rn(oacc[dt][2] * inv1, oacc[dt][3] * inv1);
    }
}

// ----------------------------------------------------------------------------
extern "C" void kernel_launch(void* const* d_in, const int* in_sizes, int n_in,
                              void* d_out, int out_size)
{
    const float* hidden = (const float*)d_in[0];
    const float* enc    = (const float*)d_in[1];
    const float* mask   = (const float*)d_in[2];
    const float* qw  = (const float*)d_in[3];
    const float* qb  = (const float*)d_in[4];
    const float* kw  = (const float*)d_in[5];
    const float* kb  = (const float*)d_in[6];
    const float* vw  = (const float*)d_in[7];
    const float* vb  = (const float*)d_in[8];
    const float* nq  = (const float*)d_in[9];
    const float* nk  = (const float*)d_in[10];
    const float* akw = (const float*)d_in[13];
    const float* akb = (const float*)d_in[14];
    const float* avw = (const float*)d_in[15];
    const float* avb = (const float*)d_in[16];
    const float* nak = (const float*)d_in[18];
    const float* ow  = (const float*)d_in[19];
    const float* ob  = (const float*)d_in[20];
    float* outp = (float*)d_out;

    __half* h16 = 0;
    __half* e16 = 0;
    __half* w16 = 0;
    __half* Q16 = 0;
    __half* K16 = 0;
    __half* V16 = 0;
    __half* AO16 = 0;
    float* Qf = 0;
    float* Kf = 0;
    cudaGetSymbolAddress((void**)&h16,  g_h16);
    cudaGetSymbolAddress((void**)&e16,  g_e16);
    cudaGetSymbolAddress((void**)&w16,  g_w16);
    cudaGetSymbolAddress((void**)&Qf,   g_Qf);
    cudaGetSymbolAddress((void**)&Kf,   g_Kf);
    cudaGetSymbolAddress((void**)&Q16,  g_Q16);
    cudaGetSymbolAddress((void**)&K16,  g_K16);
    cudaGetSymbolAddress((void**)&V16,  g_V16);
    cudaGetSymbolAddress((void**)&AO16, g_AO16);

    __half* wq16  = w16 + 0 * (size_t)MD * MD;
    __half* wk16  = w16 + 1 * (size_t)MD * MD;
    __half* wv16  = w16 + 2 * (size_t)MD * MD;
    __half* wak16 = w16 + 3 * (size_t)MD * MD;
    __half* wav16 = w16 + 4 * (size_t)MD * MD;
    __half* wo16  = w16 + 5 * (size_t)MD * MD;

    const int nw4 = MD * MD / 4;
    const int nh4 = SHID * MD / 4;
    const int ne4 = SENC * MD / 4;

    CvtJobs jobs;
    jobs.src[0] = hidden;  jobs.dst[0] = h16;   jobs.n4[0] = nh4;
    jobs.src[1] = enc;     jobs.dst[1] = e16;   jobs.n4[1] = ne4;
    jobs.src[2] = qw;      jobs.dst[2] = wq16;  jobs.n4[2] = nw4;
    jobs.src[3] = kw;      jobs.dst[3] = wk16;  jobs.n4[3] = nw4;
    jobs.src[4] = vw;      jobs.dst[4] = wv16;  jobs.n4[4] = nw4;
    jobs.src[5] = akw;     jobs.dst[5] = wak16; jobs.n4[5] = nw4;
    jobs.src[6] = avw;     jobs.dst[6] = wav16; jobs.n4[6] = nw4;
    jobs.src[7] = ow;      jobs.dst[7] = wo16;  jobs.n4[7] = nw4;

    int maxB = (nh4 + 255) / 256;
    dim3 cgrid(maxB, 8, 1);
    dim3 cblk(256, 1, 1);
    cvt_multi<<<cgrid, cblk>>>(jobs);

    dim3 blk(256, 1, 1);
    dim3 gHid(MD / 128, SHID / 128, 1);
    dim3 gEnc(MD / 128, SENC / 128, 1);

    gemm_f16<<<gHid, blk>>>(h16, wq16, qb, Qf, SHID, MD, MD, 0);
    gemm_f16<<<gHid, blk>>>(h16, wk16, kb, Kf, SHID, MD, MD, 0);
    gemm_f16<<<gHid, blk>>>(h16, wv16, vb, V16, SHID, MD, MD, 1);
    gemm_f16<<<gEnc, blk>>>(e16, wak16, akb, Kf + (size_t)SHID * MD, SENC, MD, MD, 0);
    gemm_f16<<<gEnc, blk>>>(e16, wav16, avb, V16 + (size_t)SHID * MD, SENC, MD, MD, 1);

    // Q gets the 1/sqrt(HDIM)=0.125 attention scale folded in.
    dim3 rblk(256, 1, 1);
    dim3 gr1((SHID * NHEAD) / 8, 1, 1);
    dim3 gr2((SENC * NHEAD) / 8, 1, 1);
    rmsnorm_f32_f16<<<gr1, rblk>>>(Qf, nq, Q16, SHID * NHEAD, 0.125f);
    rmsnorm_f32_f16<<<gr1, rblk>>>(Kf, nk, K16, SHID * NHEAD, 1.0f);
    rmsnorm_f32_f16<<<gr2, rblk>>>(Kf + (size_t)SHID * MD, nak,
                                   K16 + (size_t)SHID * MD, SENC * NHEAD, 1.0f);

    dim3 gF(SHID / 128, NHEAD, 1);
    dim3 fblk(256, 1, 1);
    flash16<<<gF, fblk>>>(Q16, K16, V16, mask, AO16);

    gemm_f16<<<gHid, blk>>>(AO16, wo16, ob, outp, SHID, MD, MD, 0);
}

// round 7
// speedup vs baseline: 7.6707x; 1.3101x over previous
#include <cuda_runtime.h>
#include <cuda_fp16.h>
#include <stdint.h>
#include <math.h>

typedef unsigned int u32;

#define MD    1536
#define SHID  2048
#define SENC  256
#define TTOT  2304
#define NHEAD 24
#define HDIM  64

// ---------------- scratch (__device__ globals: allocation-free rule) --------
__device__ __half g_h16 [SHID * MD];
__device__ __half g_e16 [SENC * MD];
__device__ __half g_w16 [6 * MD * MD];
__device__ float  g_Qf  [SHID * MD];
__device__ float  g_Kf  [TTOT * MD];
__device__ __half g_Q16 [SHID * MD];
__device__ __half g_K16 [TTOT * MD];
__device__ __half g_V16 [TTOT * MD];
__device__ __half g_AO16[SHID * MD];

// ---------------- small helpers --------------------------------------------
__device__ __forceinline__ void ldsm4(u32* r, u32 addr)
{
    asm volatile("ldmatrix.sync.aligned.m8n8.x4.shared.b16 {%0,%1,%2,%3}, [%4];"
                 : "=r"(r[0]), "=r"(r[1]), "=r"(r[2]), "=r"(r[3]) : "r"(addr));
}

__device__ __forceinline__ void ldsm4t(u32* r, u32 addr)
{
    asm volatile("ldmatrix.sync.aligned.m8n8.x4.trans.shared.b16 {%0,%1,%2,%3}, [%4];"
                 : "=r"(r[0]), "=r"(r[1]), "=r"(r[2]), "=r"(r[3]) : "r"(addr));
}

__device__ __forceinline__ void mma16816(float* c, const u32* a, u32 b0, u32 b1)
{
    asm volatile(
        "mma.sync.aligned.m16n8k16.row.col.f32.f16.f16.f32 "
        "{%0,%1,%2,%3}, {%4,%5,%6,%7}, {%8,%9}, {%0,%1,%2,%3};"
        : "+f"(c[0]), "+f"(c[1]), "+f"(c[2]), "+f"(c[3])
        : "r"(a[0]), "r"(a[1]), "r"(a[2]), "r"(a[3]), "r"(b0), "r"(b1));
}

__device__ __forceinline__ u32 packh2(float x, float y)
{
    __half2 h = __floats2half2_rn(x, y);
    return *reinterpret_cast<u32*>(&h);
}

__device__ __forceinline__ void cp16(u32 smem_dst, const void* gmem_src)
{
    asm volatile("cp.async.cg.shared.global [%0], [%1], 16;"
                 :: "r"(smem_dst), "l"(gmem_src));
}

__device__ __forceinline__ void cp_commit()
{
    asm volatile("cp.async.commit_group;");
}

__device__ __forceinline__ void cp_wait1()
{
    asm volatile("cp.async.wait_group 1;");
}

__device__ __forceinline__ void cp_wait0()
{
    asm volatile("cp.async.wait_group 0;");
}

// ---------------- merged fp32 -> fp16 convert (one launch, 8 segments) -----
struct CvtJobs
{
    const float* src[8];
    __half*      dst[8];
    int          n4[8];
};

__global__ __launch_bounds__(256) void cvt_multi(CvtJobs jobs)
{
    int seg = blockIdx.y;
    const float* __restrict__ src = jobs.src[seg];
    __half* __restrict__ dst = jobs.dst[seg];
    int n4 = jobs.n4[seg];
    int i = blockIdx.x * 256 + threadIdx.x;
    if (i >= n4) return;
    float4 v = ((const float4*)src)[i];
    ((__half2*)dst)[2 * i + 0] = __floats2half2_rn(v.x, v.y);
    ((__half2*)dst)[2 * i + 1] = __floats2half2_rn(v.z, v.w);
}

// ---------------- fused multi-weight fp16 GEMM ------------------------------
// C[z] = A[M,K] @ W[z][N,K]^T + bias[z].  blockIdx.z selects the weight.
// BM=128, BN=128, BK=32, 256 threads (8 warps: 2 m x 4 n), warp tile 64x32.
// 2-stage cp.async double buffer.
struct GemmJob
{
    const __half* A;
    const __half* W[3];
    const float*  bias[3];
    void*         C[3];
    int           out_half[3];
};

__global__ __launch_bounds__(256) void gemm_multi(GemmJob job, int M, int N, int K)
{
    __shared__ __align__(16) __half As[2][128][40];
    __shared__ __align__(16) __half Bs[2][128][40];
    const int z = blockIdx.z;
    const __half* __restrict__ A = job.A;
    const __half* __restrict__ W = job.W[z];
    const float* __restrict__ bias = job.bias[z];
    void* Cout = job.C[z];
    const int out_half = job.out_half[z];

    const int bm = blockIdx.y * 128;
    const int bn = blockIdx.x * 128;
    const int tid  = threadIdx.x;
    const int lane = tid & 31;
    const int warp = tid >> 5;
    const int wm  = warp & 1;
    const int wn  = warp >> 1;
    const int oct = lane >> 3;
    const int oj  = lane & 7;

    const u32 sA = (u32)__cvta_generic_to_shared(&As[0][0][0]);
    const u32 sB = (u32)__cvta_generic_to_shared(&Bs[0][0][0]);
    const u32 stageBytes = 128 * 40 * 2;

    float acc[4][4][4];
    #pragma unroll
    for (int mi = 0; mi < 4; mi++)
        #pragma unroll
        for (int ni = 0; ni < 4; ni++)
            #pragma unroll
            for (int x = 0; x < 4; x++) acc[mi][ni][x] = 0.0f;

    const int lr = tid >> 2;
    const int lc = (tid & 3) * 8;

    const int KT = K >> 5;

    {
        u32 dA = sA + (u32)(lr * 40 + lc) * 2u;
        cp16(dA, A + (size_t)(bm + lr) * K + lc);
        cp16(dA + 64u * 80u, A + (size_t)(bm + lr + 64) * K + lc);
        u32 dB = sB + (u32)(lr * 40 + lc) * 2u;
        cp16(dB, W + (size_t)(bn + lr) * K + lc);
        cp16(dB + 64u * 80u, W + (size_t)(bn + lr + 64) * K + lc);
        cp_commit();
    }

    for (int kt = 0; kt < KT; kt++)
    {
        if (kt + 1 < KT)
        {
            const int k0 = (kt + 1) << 5;
            const u32 so = ((kt + 1) & 1) ? stageBytes : 0u;
            u32 dA = sA + so + (u32)(lr * 40 + lc) * 2u;
            cp16(dA, A + (size_t)(bm + lr) * K + k0 + lc);
            cp16(dA + 64u * 80u, A + (size_t)(bm + lr + 64) * K + k0 + lc);
            u32 dB = sB + so + (u32)(lr * 40 + lc) * 2u;
            cp16(dB, W + (size_t)(bn + lr) * K + k0 + lc);
            cp16(dB + 64u * 80u, W + (size_t)(bn + lr + 64) * K + k0 + lc);
            cp_commit();
            cp_wait1();
        }
        else
        {
            cp_wait0();
        }
        __syncthreads();

        const u32 so = (kt & 1) ? stageBytes : 0u;
        #pragma unroll
        for (int ks = 0; ks < 2; ks++)
        {
            const int ksh = ks * 16;
            u32 af[4][4];
            #pragma unroll
            for (int mi = 0; mi < 4; mi++)
            {
                int row = wm * 64 + mi * 16 + (oct & 1) * 8 + oj;
                int col = ksh + (oct >> 1) * 8;
                ldsm4(af[mi], sA + so + (u32)(row * 40 + col) * 2u);
            }
            u32 bf[2][4];
            #pragma unroll
            for (int nb = 0; nb < 2; nb++)
            {
                int row = wn * 32 + nb * 16 + (oct >> 1) * 8 + oj;
                int col = ksh + (oct & 1) * 8;
                ldsm4(bf[nb], sB + so + (u32)(row * 40 + col) * 2u);
            }
            #pragma unroll
            for (int mi = 0; mi < 4; mi++)
            {
                #pragma unroll
                for (int nb = 0; nb < 2; nb++)
                {
                    mma16816(acc[mi][2 * nb + 0], af[mi], bf[nb][0], bf[nb][1]);
                    mma16816(acc[mi][2 * nb + 1], af[mi], bf[nb][2], bf[nb][3]);
                }
            }
        }
        __syncthreads();
    }

    #pragma unroll
    for (int mi = 0; mi < 4; mi++)
    {
        #pragma unroll
        for (int ni = 0; ni < 4; ni++)
        {
            const float* c = acc[mi][ni];
            int row = bm + wm * 64 + mi * 16 + (lane >> 2);
            int col = bn + wn * 32 + ni * 8 + (lane & 3) * 2;
            float b0 = bias[col];
            float b1 = bias[col + 1];
            if (out_half)
            {
                __half* C = (__half*)Cout;
                *(__half2*)(C + (size_t)row * N + col) =
                    __floats2half2_rn(c[0] + b0, c[1] + b1);
                *(__half2*)(C + (size_t)(row + 8) * N + col) =
                    __floats2half2_rn(c[2] + b0, c[3] + b1);
            }
            else
            {
                float* C = (float*)Cout;
                *(float2*)(C + (size_t)row * N + col) = make_float2(c[0] + b0, c[1] + b1);
                *(float2*)(C + (size_t)(row + 8) * N + col) = make_float2(c[2] + b0, c[3] + b1);
            }
        }
    }
}

// ---------------- merged per-head RMSNorm (Q + K both streams) --------------
__global__ __launch_bounds__(256) void rmsnorm_all(
    const float* __restrict__ Qf, const float* __restrict__ Kf,
    const float* __restrict__ nq, const float* __restrict__ nk,
    const float* __restrict__ nak,
    __half* __restrict__ Q16, __half* __restrict__ K16)
{
    const int NQ = SHID * NHEAD;
    const int NK = TTOT * NHEAD;
    int task = (blockIdx.x * blockDim.x + threadIdx.x) >> 5;
    int lane = threadIdx.x & 31;
    if (task >= NQ + NK) return;

    const float* X;
    __half* Y;
    const float* w;
    float outscale;
    int row, h;
    if (task < NQ)
    {
        row = task / NHEAD;
        h   = task % NHEAD;
        X = Qf; Y = Q16; w = nq; outscale = 0.125f;
    }
    else
    {
        int t2 = task - NQ;
        row = t2 / NHEAD;
        h   = t2 % NHEAD;
        X = Kf; Y = K16;
        w = (row < SHID) ? nk : nak;
        outscale = 1.0f;
    }
    const float* p = X + (size_t)row * MD + h * HDIM;
    float2 v = ((const float2*)p)[lane];
    float ss = v.x * v.x + v.y * v.y;
    #pragma unroll
    for (int o = 16; o; o >>= 1) ss += __shfl_xor_sync(0xffffffffu, ss, o);
    float r = rsqrtf(ss * (1.0f / HDIM) + 1e-6f) * outscale;
    __half2* q = (__half2*)(Y + (size_t)row * MD + h * HDIM);
    q[lane] = __floats2half2_rn(v.x * r * w[2 * lane], v.y * r * w[2 * lane + 1]);
}

// ---------------- fp16 flash attention (tensor core, cp.async K/V) ----------
// 256 threads = 8 warps; q-tile 128 (16 rows/warp), kv-tile 64, d=64.
// Dynamic smem: Qs[128][72] | Ks[2][64][72] | Vs[2][64][72] | smask[64]
#define FQ_OFF   0
#define FK_OFF   18432
#define FV_OFF   36864
#define FM_OFF   55296
#define F_SMEM   55552
#define KV_STAGE 9216

__global__ __launch_bounds__(256) void flash16(
    const __half* __restrict__ Qg, const __half* __restrict__ Kg,
    const __half* __restrict__ Vg, const float* __restrict__ mask,
    __half* __restrict__ AO)
{
    extern __shared__ __align__(16) char fsm[];
    __half* Qs = (__half*)(fsm + FQ_OFF);
    float* smask = (float*)(fsm + FM_OFF);

    const int h  = blockIdx.y;
    const int bq = blockIdx.x * 128;
    const int tid  = threadIdx.x;
    const int lane = tid & 31;
    const int warp = tid >> 5;
    const int oct = lane >> 3;
    const int oj  = lane & 7;
    const int cb  = (lane & 3) * 2;

    const u32 smemBase = (u32)__cvta_generic_to_shared(fsm);
    const u32 sQ = smemBase + FQ_OFF;
    const u32 sK = smemBase + FK_OFF;
    const u32 sV = smemBase + FV_OFF;

    // load Q tile (regular stores, once)
    #pragma unroll
    for (int l = 0; l < 4; l++)
    {
        int idx = tid + l * 256;
        int r  = idx >> 3;
        int cc = (idx & 7) * 8;
        *(int4*)(Qs + r * 72 + cc) =
            *(const int4*)(Qg + (size_t)(bq + r) * MD + h * HDIM + cc);
    }

    // preload kv tile 0 into stage 0
    {
        #pragma unroll
        for (int l = 0; l < 2; l++)
        {
            int idx = tid + l * 256;
            int r  = idx >> 3;
            int cc = (idx & 7) * 8;
            cp16(sK + (u32)(r * 72 + cc) * 2u, Kg + (size_t)r * MD + h * HDIM + cc);
            cp16(sV + (u32)(r * 72 + cc) * 2u, Vg + (size_t)r * MD + h * HDIM + cc);
        }
        cp_commit();
    }

    __syncthreads();
    u32 qa[4][4];
    #pragma unroll
    for (int kf = 0; kf < 4; kf++)
    {
        int row = warp * 16 + (oct & 1) * 8 + oj;
        int col = kf * 16 + (oct >> 1) * 8;
        ldsm4(qa[kf], sQ + (u32)(row * 72 + col) * 2u);
    }

    float m0 = -1e30f;
    float m1 = -1e30f;
    float l0 = 0.0f;
    float l1 = 0.0f;
    float oacc[8][4];
    #pragma unroll
    for (int dt = 0; dt < 8; dt++)
    {
        #pragma unroll
        for (int x = 0; x < 4; x++) oacc[dt][x] = 0.0f;
    }

    const int NT = TTOT / 64;
    for (int t = 0; t < NT; t++)
    {
        if (t + 1 < NT)
        {
            const u32 so = (u32)((t + 1) & 1) * KV_STAGE;
            #pragma unroll
            for (int l = 0; l < 2; l++)
            {
                int idx = tid + l * 256;
                int r  = idx >> 3;
                int cc = (idx & 7) * 8;
                cp16(sK + so + (u32)(r * 72 + cc) * 2u,
                     Kg + (size_t)((t + 1) * 64 + r) * MD + h * HDIM + cc);
                cp16(sV + so + (u32)(r * 72 + cc) * 2u,
                     Vg + (size_t)((t + 1) * 64 + r) * MD + h * HDIM + cc);
            }
            cp_commit();
            cp_wait1();
        }
        else
        {
            cp_wait0();
        }
        if (tid < 64) smask[tid] = mask[t * 64 + tid];
        __syncthreads();

        const u32 so = (u32)(t & 1) * KV_STAGE;

        // S = Q @ K^T
        float s[8][4];
        #pragma unroll
        for (int jt = 0; jt < 8; jt++)
        {
            #pragma unroll
            for (int x = 0; x < 4; x++) s[jt][x] = 0.0f;
        }
        #pragma unroll
        for (int nb = 0; nb < 4; nb++)
        {
            #pragma unroll
            for (int kf = 0; kf < 4; kf++)
            {
                u32 bf[4];
                int row = nb * 16 + (oct >> 1) * 8 + oj;
                int col = kf * 16 + (oct & 1) * 8;
                ldsm4(bf, sK + so + (u32)(row * 72 + col) * 2u);
                mma16816(s[2 * nb + 0], qa[kf], bf[0], bf[1]);
                mma16816(s[2 * nb + 1], qa[kf], bf[2], bf[3]);
            }
        }

        // mask + online softmax
        float mx0 = -1e30f;
        float mx1 = -1e30f;
        #pragma unroll
        for (int jt = 0; jt < 8; jt++)
        {
            float mk0 = smask[jt * 8 + cb];
            float mk1 = smask[jt * 8 + cb + 1];
            s[jt][0] += mk0;
            s[jt][1] += mk1;
            s[jt][2] += mk0;
            s[jt][3] += mk1;
            mx0 = fmaxf(mx0, fmaxf(s[jt][0], s[jt][1]));
            mx1 = fmaxf(mx1, fmaxf(s[jt][2], s[jt][3]));
        }
        mx0 = fmaxf(mx0, __shfl_xor_sync(0xffffffffu, mx0, 1));
        mx0 = fmaxf(mx0, __shfl_xor_sync(0xffffffffu, mx0, 2));
        mx1 = fmaxf(mx1, __shfl_xor_sync(0xffffffffu, mx1, 1));
        mx1 = fmaxf(mx1, __shfl_xor_sync(0xffffffffu, mx1, 2));
        float mn0 = fmaxf(m0, mx0);
        float a0  = __expf(m0 - mn0);
        m0 = mn0;
        float mn1 = fmaxf(m1, mx1);
        float a1  = __expf(m1 - mn1);
        m1 = mn1;

        float rs0 = 0.0f;
        float rs1 = 0.0f;
        #pragma unroll
        for (int jt = 0; jt < 8; jt++)
        {
            s[jt][0] = __expf(s[jt][0] - m0); rs0 += s[jt][0];
            s[jt][1] = __expf(s[jt][1] - m0); rs0 += s[jt][1];
            s[jt][2] = __expf(s[jt][2] - m1); rs1 += s[jt][2];
            s[jt][3] = __expf(s[jt][3] - m1); rs1 += s[jt][3];
        }
        l0 = l0 * a0 + rs0;
        l1 = l1 * a1 + rs1;

        // P fragments (A operand for P@V)
        u32 pa[4][4];
        #pragma unroll
        for (int kf = 0; kf < 4; kf++)
        {
            pa[kf][0] = packh2(s[2 * kf + 0][0], s[2 * kf + 0][1]);
            pa[kf][1] = packh2(s[2 * kf + 0][2], s[2 * kf + 0][3]);
            pa[kf][2] = packh2(s[2 * kf + 1][0], s[2 * kf + 1][1]);
            pa[kf][3] = packh2(s[2 * kf + 1][2], s[2 * kf + 1][3]);
        }
        #pragma unroll
        for (int dt = 0; dt < 8; dt++)
        {
            oacc[dt][0] *= a0;
            oacc[dt][1] *= a0;
            oacc[dt][2] *= a1;
            oacc[dt][3] *= a1;
        }
        // O += P @ V (B via ldmatrix.trans on Vs[kv][d])
        #pragma unroll
        for (int db = 0; db < 4; db++)
        {
            #pragma unroll
            for (int kf = 0; kf < 4; kf++)
            {
                u32 bf[4];
                int row = kf * 16 + (oct & 1) * 8 + oj;
                int col = db * 16 + (oct >> 1) * 8;
                ldsm4t(bf, sV + so + (u32)(row * 72 + col) * 2u);
                mma16816(oacc[2 * db + 0], pa[kf], bf[0], bf[1]);
                mma16816(oacc[2 * db + 1], pa[kf], bf[2], bf[3]);
            }
        }
        __syncthreads();
    }

    l0 += __shfl_xor_sync(0xffffffffu, l0, 1);
    l0 += __shfl_xor_sync(0xffffffffu, l0, 2);
    l1 += __shfl_xor_sync(0xffffffffu, l1, 1);
    l1 += __shfl_xor_sync(0xffffffffu, l1, 2);
    float inv0 = 1.0f / l0;
    float inv1 = 1.0f / l1;

    #pragma unroll
    for (int dt = 0; dt < 8; dt++)
    {
        int row = bq + warp * 16 + (lane >> 2);
        int col = h * HDIM + dt * 8 + cb;
        *(__half2*)(AO + (size_t)row * MD + col) =
            __floats2half2_rn(oacc[dt][0] * inv0, oacc[dt][1] * inv0);
        *(__half2*)(AO + (size_t)(row + 8) * MD + col) =
            __floats2half2_rn(oacc[dt][2] * inv1, oacc[dt][3] * inv1);
    }
}

// ----------------------------------------------------------------------------
extern "C" void kernel_launch(void* const* d_in, const int* in_sizes, int n_in,
                              void* d_out, int out_size)
{
    const float* hidden = (const float*)d_in[0];
    const float* enc    = (const float*)d_in[1];
    const float* mask   = (const float*)d_in[2];
    const float* qw  = (const float*)d_in[3];
    const float* qb  = (const float*)d_in[4];
    const float* kw  = (const float*)d_in[5];
    const float* kb  = (const float*)d_in[6];
    const float* vw  = (const float*)d_in[7];
    const float* vb  = (const float*)d_in[8];
    const float* nq  = (const float*)d_in[9];
    const float* nk  = (const float*)d_in[10];
    const float* akw = (const float*)d_in[13];
    const float* akb = (const float*)d_in[14];
    const float* avw = (const float*)d_in[15];
    const float* avb = (const float*)d_in[16];
    const float* nak = (const float*)d_in[18];
    const float* ow  = (const float*)d_in[19];
    const float* ob  = (const float*)d_in[20];
    float* outp = (float*)d_out;

    __half* h16 = 0;
    __half* e16 = 0;
    __half* w16 = 0;
    __half* Q16 = 0;
    __half* K16 = 0;
    __half* V16 = 0;
    __half* AO16 = 0;
    float* Qf = 0;
    float* Kf = 0;
    cudaGetSymbolAddress((void**)&h16,  g_h16);
    cudaGetSymbolAddress((void**)&e16,  g_e16);
    cudaGetSymbolAddress((void**)&w16,  g_w16);
    cudaGetSymbolAddress((void**)&Qf,   g_Qf);
    cudaGetSymbolAddress((void**)&Kf,   g_Kf);
    cudaGetSymbolAddress((void**)&Q16,  g_Q16);
    cudaGetSymbolAddress((void**)&K16,  g_K16);
    cudaGetSymbolAddress((void**)&V16,  g_V16);
    cudaGetSymbolAddress((void**)&AO16, g_AO16);

    __half* wq16  = w16 + 0 * (size_t)MD * MD;
    __half* wk16  = w16 + 1 * (size_t)MD * MD;
    __half* wv16  = w16 + 2 * (size_t)MD * MD;
    __half* wak16 = w16 + 3 * (size_t)MD * MD;
    __half* wav16 = w16 + 4 * (size_t)MD * MD;
    __half* wo16  = w16 + 5 * (size_t)MD * MD;

    const int nw4 = MD * MD / 4;
    const int nh4 = SHID * MD / 4;
    const int ne4 = SENC * MD / 4;

    CvtJobs jobs;
    jobs.src[0] = hidden;  jobs.dst[0] = h16;   jobs.n4[0] = nh4;
    jobs.src[1] = enc;     jobs.dst[1] = e16;   jobs.n4[1] = ne4;
    jobs.src[2] = qw;      jobs.dst[2] = wq16;  jobs.n4[2] = nw4;
    jobs.src[3] = kw;      jobs.dst[3] = wk16;  jobs.n4[3] = nw4;
    jobs.src[4] = vw;      jobs.dst[4] = wv16;  jobs.n4[4] = nw4;
    jobs.src[5] = akw;     jobs.dst[5] = wak16; jobs.n4[5] = nw4;
    jobs.src[6] = avw;     jobs.dst[6] = wav16; jobs.n4[6] = nw4;
    jobs.src[7] = ow;      jobs.dst[7] = wo16;  jobs.n4[7] = nw4;

    int maxB = (nh4 + 255) / 256;
    dim3 cgrid(maxB, 8, 1);
    dim3 cblk(256, 1, 1);
    cvt_multi<<<cgrid, cblk>>>(jobs);

    dim3 blk(256, 1, 1);

    // fused hidden-stream QKV (one launch, 576 blocks)
    GemmJob jQKV;
    jQKV.A = h16;
    jQKV.W[0] = wq16;  jQKV.bias[0] = qb;  jQKV.C[0] = Qf;   jQKV.out_half[0] = 0;
    jQKV.W[1] = wk16;  jQKV.bias[1] = kb;  jQKV.C[1] = Kf;   jQKV.out_half[1] = 0;
    jQKV.W[2] = wv16;  jQKV.bias[2] = vb;  jQKV.C[2] = V16;  jQKV.out_half[2] = 1;
    dim3 gQKV(MD / 128, SHID / 128, 3);
    gemm_multi<<<gQKV, blk>>>(jQKV, SHID, MD, MD);

    // fused encoder-stream K/V (one launch)
    GemmJob jE;
    jE.A = e16;
    jE.W[0] = wak16;  jE.bias[0] = akb;  jE.C[0] = Kf + (size_t)SHID * MD;   jE.out_half[0] = 0;
    jE.W[1] = wav16;  jE.bias[1] = avb;  jE.C[1] = V16 + (size_t)SHID * MD;  jE.out_half[1] = 1;
    jE.W[2] = wak16;  jE.bias[2] = akb;  jE.C[2] = Kf + (size_t)SHID * MD;   jE.out_half[2] = 0;
    dim3 gE(MD / 128, SENC / 128, 2);
    gemm_multi<<<gE, blk>>>(jE, SENC, MD, MD);

    // merged RMSNorm (Q hidden + K both streams), one launch
    {
        int ntasks = SHID * NHEAD + TTOT * NHEAD;
        dim3 rgrid((ntasks + 7) / 8, 1, 1);
        dim3 rblk(256, 1, 1);
        rmsnorm_all<<<rgrid, rblk>>>(Qf, Kf, nq, nk, nak, Q16, K16);
    }

    // flash attention with cp.async double-buffered K/V
    static int flashAttrSet = 0;
    if (!flashAttrSet)
    {
        cudaFuncSetAttribute(flash16, cudaFuncAttributeMaxDynamicSharedMemorySize, F_SMEM);
        flashAttrSet = 1;
    }
    dim3 gF(SHID / 128, NHEAD, 1);
    dim3 fblk(256, 1, 1);
    flash16<<<gF, fblk, F_SMEM>>>(Q16, K16, V16, mask, AO16);

    // output projection
    GemmJob jO;
    jO.A = AO16;
    jO.W[0] = wo16;  jO.bias[0] = ob;  jO.C[0] = outp;  jO.out_half[0] = 0;
    jO.W[1] = wo16;  jO.bias[1] = ob;  jO.C[1] = outp;  jO.out_half[1] = 0;
    jO.W[2] = wo16;  jO.bias[2] = ob;  jO.C[2] = outp;  jO.out_half[2] = 0;
    dim3 gO(MD / 128, SHID / 128, 1);
    gemm_multi<<<gO, blk>>>(jO, SHID, MD, MD);
}

// round 9
// speedup vs baseline: 8.0132x; 1.0446x over previous
#include <cuda_runtime.h>
#include <cuda_fp16.h>
#include <stdint.h>
#include <math.h>

typedef unsigned int u32;

#define MD    1536
#define SHID  2048
#define SENC  256
#define TTOT  2304
#define NHEAD 24
#define HDIM  64

// ---------------- scratch (__device__ globals: allocation-free rule) --------
__device__ __half g_h16 [SHID * MD];
__device__ __half g_e16 [SENC * MD];
__device__ __half g_w16 [6 * MD * MD];
__device__ __half g_Q16 [SHID * MD];
__device__ __half g_K16 [TTOT * MD];
__device__ __half g_V16 [TTOT * MD];
__device__ __half g_AO16[SHID * MD];

// ---------------- warp-mma helpers ------------------------------------------
__device__ __forceinline__ void ldsm4(u32* r, u32 addr)
{
    asm volatile("ldmatrix.sync.aligned.m8n8.x4.shared.b16 {%0,%1,%2,%3}, [%4];"
                 : "=r"(r[0]), "=r"(r[1]), "=r"(r[2]), "=r"(r[3]) : "r"(addr));
}

__device__ __forceinline__ void ldsm4t(u32* r, u32 addr)
{
    asm volatile("ldmatrix.sync.aligned.m8n8.x4.trans.shared.b16 {%0,%1,%2,%3}, [%4];"
                 : "=r"(r[0]), "=r"(r[1]), "=r"(r[2]), "=r"(r[3]) : "r"(addr));
}

__device__ __forceinline__ void mma16816(float* c, const u32* a, u32 b0, u32 b1)
{
    asm volatile(
        "mma.sync.aligned.m16n8k16.row.col.f32.f16.f16.f32 "
        "{%0,%1,%2,%3}, {%4,%5,%6,%7}, {%8,%9}, {%0,%1,%2,%3};"
        : "+f"(c[0]), "+f"(c[1]), "+f"(c[2]), "+f"(c[3])
        : "r"(a[0]), "r"(a[1]), "r"(a[2]), "r"(a[3]), "r"(b0), "r"(b1));
}

__device__ __forceinline__ u32 packh2(float x, float y)
{
    __half2 h = __floats2half2_rn(x, y);
    return *reinterpret_cast<u32*>(&h);
}

__device__ __forceinline__ void cp16(u32 smem_dst, const void* gmem_src)
{
    asm volatile("cp.async.cg.shared.global [%0], [%1], 16;"
                 :: "r"(smem_dst), "l"(gmem_src));
}

__device__ __forceinline__ void cp_commit()
{
    asm volatile("cp.async.commit_group;");
}

__device__ __forceinline__ void cp_wait1()
{
    asm volatile("cp.async.wait_group 1;");
}

__device__ __forceinline__ void cp_wait0()
{
    asm volatile("cp.async.wait_group 0;");
}

// ---------------- merged fp32 -> fp16 convert (one launch, 8 segments) -----
struct CvtJobs
{
    const float* src[8];
    __half*      dst[8];
    int          n4[8];
};

__global__ __launch_bounds__(256) void cvt_multi(CvtJobs jobs)
{
    int seg = blockIdx.y;
    const float* __restrict__ src = jobs.src[seg];
    __half* __restrict__ dst = jobs.dst[seg];
    int n4 = jobs.n4[seg];
    int i0 = (blockIdx.x * 256 + threadIdx.x) * 4;
    if (i0 >= n4) return;
    #pragma unroll
    for (int j = 0; j < 4; j++)
    {
        int i = i0 + j;
        float4 v = ((const float4*)src)[i];
        ((__half2*)dst)[2 * i + 0] = __floats2half2_rn(v.x, v.y);
        ((__half2*)dst)[2 * i + 1] = __floats2half2_rn(v.z, v.w);
    }
}

// ---------------- multi-job fp16 GEMM with fused per-head RMSNorm -----------
// C[z] = f( A[z][M,K] @ W[z][N,K]^T + bias[z] )
// mode 0: f32 out, 1: f16 out, 2: f16 out with per-64-col-head RMSNorm*scale.
// BM=128, BN=128, BK=32, 256 threads (8 warps: 2m x 4n), warp tile 64x32.
// 3-stage cp.async pipeline (dynamic smem).
struct GemmJobs
{
    const __half* A[5];
    const __half* W[5];
    const float*  bias[5];
    const float*  normw[5];
    void*         C[5];
    int           M[5];
    int           mode[5];
    float         scale[5];
};

#define GSTG_B   10240            // one stage: 128*40 halves
#define GB_OFF   30720            // 3 stages of A
#define GSSQ_OFF 61440
#define G_SMEM   63488

__global__ __launch_bounds__(256) void gemm_f16x(GemmJobs job, int N, int K)
{
    extern __shared__ __align__(16) char gsm[];
    const int z = blockIdx.z;
    const int bm = blockIdx.y * 128;
    if (bm >= job.M[z]) return;
    const __half* __restrict__ A = job.A[z];
    const __half* __restrict__ W = job.W[z];
    const float* __restrict__ bias = job.bias[z];
    const float* __restrict__ normw = job.normw[z];
    void* Cout = job.C[z];
    const int mode = job.mode[z];
    const float nscale = job.scale[z];

    const int bn = blockIdx.x * 128;
    const int tid  = threadIdx.x;
    const int lane = tid & 31;
    const int warp = tid >> 5;
    const int wm  = warp & 1;
    const int wn  = warp >> 1;
    const int oct = lane >> 3;
    const int oj  = lane & 7;

    const u32 sA = (u32)__cvta_generic_to_shared(gsm);
    const u32 sB = sA + GB_OFF;

    float acc[4][4][4];
    #pragma unroll
    for (int mi = 0; mi < 4; mi++)
        #pragma unroll
        for (int ni = 0; ni < 4; ni++)
            #pragma unroll
            for (int x = 0; x < 4; x++) acc[mi][ni][x] = 0.0f;

    const int lr = tid >> 2;
    const int lc = (tid & 3) * 8;

    const int KT = K >> 5;

    // prologue: tiles 0, 1
    #pragma unroll
    for (int pt = 0; pt < 2; pt++)
    {
        const u32 so = (u32)pt * GSTG_B;
        u32 dA = sA + so + (u32)(lr * 40 + lc) * 2u;
        cp16(dA, A + (size_t)(bm + lr) * K + pt * 32 + lc);
        cp16(dA + 64u * 80u, A + (size_t)(bm + lr + 64) * K + pt * 32 + lc);
        u32 dB = sB + so + (u32)(lr * 40 + lc) * 2u;
        cp16(dB, W + (size_t)(bn + lr) * K + pt * 32 + lc);
        cp16(dB + 64u * 80u, W + (size_t)(bn + lr + 64) * K + pt * 32 + lc);
        cp_commit();
    }

    for (int kt = 0; kt < KT; kt++)
    {
        if (kt == KT - 1) cp_wait0(); else cp_wait1();
        __syncthreads();

        if (kt + 2 < KT)
        {
            const int nt = kt + 2;
            const u32 so = (u32)(nt % 3) * GSTG_B;
            u32 dA = sA + so + (u32)(lr * 40 + lc) * 2u;
            cp16(dA, A + (size_t)(bm + lr) * K + nt * 32 + lc);
            cp16(dA + 64u * 80u, A + (size_t)(bm + lr + 64) * K + nt * 32 + lc);
            u32 dB = sB + so + (u32)(lr * 40 + lc) * 2u;
            cp16(dB, W + (size_t)(bn + lr) * K + nt * 32 + lc);
            cp16(dB + 64u * 80u, W + (size_t)(bn + lr + 64) * K + nt * 32 + lc);
            cp_commit();
        }

        const u32 so = (u32)(kt % 3) * GSTG_B;
        #pragma unroll
        for (int ks = 0; ks < 2; ks++)
        {
            const int ksh = ks * 16;
            u32 af[4][4];
            #pragma unroll
            for (int mi = 0; mi < 4; mi++)
            {
                int row = wm * 64 + mi * 16 + (oct & 1) * 8 + oj;
                int col = ksh + (oct >> 1) * 8;
                ldsm4(af[mi], sA + so + (u32)(row * 40 + col) * 2u);
            }
            u32 bf[2][4];
            #pragma unroll
            for (int nb = 0; nb < 2; nb++)
            {
                int row = wn * 32 + nb * 16 + (oct >> 1) * 8 + oj;
                int col = ksh + (oct & 1) * 8;
                ldsm4(bf[nb], sB + so + (u32)(row * 40 + col) * 2u);
            }
            #pragma unroll
            for (int mi = 0; mi < 4; mi++)
            {
                #pragma unroll
                for (int nb = 0; nb < 2; nb++)
                {
                    mma16816(acc[mi][2 * nb + 0], af[mi], bf[nb][0], bf[nb][1]);
                    mma16816(acc[mi][2 * nb + 1], af[mi], bf[nb][2], bf[nb][3]);
                }
            }
        }
    }

    // ---- epilogue ----
    // add bias into accumulators
    #pragma unroll
    for (int ni = 0; ni < 4; ni++)
    {
        int col = bn + wn * 32 + ni * 8 + (lane & 3) * 2;
        float b0 = bias[col];
        float b1 = bias[col + 1];
        #pragma unroll
        for (int mi = 0; mi < 4; mi++)
        {
            acc[mi][ni][0] += b0;
            acc[mi][ni][1] += b1;
            acc[mi][ni][2] += b0;
            acc[mi][ni][3] += b1;
        }
    }

    if (mode == 2)
    {
        // fused per-head RMSNorm: head = 64 cols = warp pair (wn&~1, wn|1)
        float* ssq = (float*)(gsm + GSSQ_OFF);
        __syncthreads();   // smem tiles no longer needed
        #pragma unroll
        for (int mi = 0; mi < 4; mi++)
        {
            float s0 = 0.0f;
            float s1 = 0.0f;
            #pragma unroll
            for (int ni = 0; ni < 4; ni++)
            {
                s0 += acc[mi][ni][0] * acc[mi][ni][0] + acc[mi][ni][1] * acc[mi][ni][1];
                s1 += acc[mi][ni][2] * acc[mi][ni][2] + acc[mi][ni][3] * acc[mi][ni][3];
            }
            s0 += __shfl_xor_sync(0xffffffffu, s0, 1);
            s0 += __shfl_xor_sync(0xffffffffu, s0, 2);
            s1 += __shfl_xor_sync(0xffffffffu, s1, 1);
            s1 += __shfl_xor_sync(0xffffffffu, s1, 2);
            if ((lane & 3) == 0)
            {
                int r0 = wm * 64 + mi * 16 + (lane >> 2);
                ssq[r0 * 4 + wn] = s0;
                ssq[(r0 + 8) * 4 + wn] = s1;
            }
        }
        __syncthreads();
        __half* C = (__half*)Cout;
        const int wp = wn & ~1;
        #pragma unroll
        for (int mi = 0; mi < 4; mi++)
        {
            int r0 = wm * 64 + mi * 16 + (lane >> 2);
            int r1 = r0 + 8;
            float t0 = ssq[r0 * 4 + wp] + ssq[r0 * 4 + wp + 1];
            float t1 = ssq[r1 * 4 + wp] + ssq[r1 * 4 + wp + 1];
            float rs0 = rsqrtf(t0 * (1.0f / HDIM) + 1e-6f) * nscale;
            float rs1 = rsqrtf(t1 * (1.0f / HDIM) + 1e-6f) * nscale;
            #pragma unroll
            for (int ni = 0; ni < 4; ni++)
            {
                int wcol = (wn * 32 + ni * 8 + (lane & 3) * 2) & 63;
                float w0 = normw[wcol];
                float w1 = normw[wcol + 1];
                int row = bm + r0;
                int col = bn + wn * 32 + ni * 8 + (lane & 3) * 2;
                *(__half2*)(C + (size_t)row * N + col) =
                    __floats2half2_rn(acc[mi][ni][0] * rs0 * w0, acc[mi][ni][1] * rs0 * w1);
                *(__half2*)(C + (size_t)(bm + r1) * N + col) =
                    __floats2half2_rn(acc[mi][ni][2] * rs1 * w0, acc[mi][ni][3] * rs1 * w1);
            }
        }
    }
    else if (mode == 1)
    {
        __half* C = (__half*)Cout;
        #pragma unroll
        for (int mi = 0; mi < 4; mi++)
        {
            #pragma unroll
            for (int ni = 0; ni < 4; ni++)
            {
                int row = bm + wm * 64 + mi * 16 + (lane >> 2);
                int col = bn + wn * 32 + ni * 8 + (lane & 3) * 2;
                *(__half2*)(C + (size_t)row * N + col) =
                    __floats2half2_rn(acc[mi][ni][0], acc[mi][ni][1]);
                *(__half2*)(C + (size_t)(row + 8) * N + col) =
                    __floats2half2_rn(acc[mi][ni][2], acc[mi][ni][3]);
            }
        }
    }
    else
    {
        float* C = (float*)Cout;
        #pragma unroll
        for (int mi = 0; mi < 4; mi++)
        {
            #pragma unroll
            for (int ni = 0; ni < 4; ni++)
            {
                int row = bm + wm * 64 + mi * 16 + (lane >> 2);
                int col = bn + wn * 32 + ni * 8 + (lane & 3) * 2;
                *(float2*)(C + (size_t)row * N + col) =
                    make_float2(acc[mi][ni][0], acc[mi][ni][1]);
                *(float2*)(C + (size_t)(row + 8) * N + col) =
                    make_float2(acc[mi][ni][2], acc[mi][ni][3]);
            }
        }
    }
}

// ---------------- fp16 flash attention (tensor core, cp.async K/V) ----------
#define FQ_OFF   0
#define FK_OFF   18432
#define FV_OFF   36864
#define FM_OFF   55296
#define F_SMEM   55552
#define KV_STAGE 9216

__global__ __launch_bounds__(256) void flash16(
    const __half* __restrict__ Qg, const __half* __restrict__ Kg,
    const __half* __restrict__ Vg, const float* __restrict__ mask,
    __half* __restrict__ AO)
{
    extern __shared__ __align__(16) char fsm[];
    __half* Qs = (__half*)(fsm + FQ_OFF);
    float* smask = (float*)(fsm + FM_OFF);

    const int h  = blockIdx.y;
    const int bq = blockIdx.x * 128;
    const int tid  = threadIdx.x;
    const int lane = tid & 31;
    const int warp = tid >> 5;
    const int oct = lane >> 3;
    const int oj  = lane & 7;
    const int cb  = (lane & 3) * 2;

    const u32 smemBase = (u32)__cvta_generic_to_shared(fsm);
    const u32 sQ = smemBase + FQ_OFF;
    const u32 sK = smemBase + FK_OFF;
    const u32 sV = smemBase + FV_OFF;

    #pragma unroll
    for (int l = 0; l < 4; l++)
    {
        int idx = tid + l * 256;
        int r  = idx >> 3;
        int cc = (idx & 7) * 8;
        *(int4*)(Qs + r * 72 + cc) =
            *(const int4*)(Qg + (size_t)(bq + r) * MD + h * HDIM + cc);
    }

    {
        #pragma unroll
        for (int l = 0; l < 2; l++)
        {
            int idx = tid + l * 256;
            int r  = idx >> 3;
            int cc = (idx & 7) * 8;
            cp16(sK + (u32)(r * 72 + cc) * 2u, Kg + (size_t)r * MD + h * HDIM + cc);
            cp16(sV + (u32)(r * 72 + cc) * 2u, Vg + (size_t)r * MD + h * HDIM + cc);
        }
        cp_commit();
    }

    __syncthreads();
    u32 qa[4][4];
    #pragma unroll
    for (int kf = 0; kf < 4; kf++)
    {
        int row = warp * 16 + (oct & 1) * 8 + oj;
        int col = kf * 16 + (oct >> 1) * 8;
        ldsm4(qa[kf], sQ + (u32)(row * 72 + col) * 2u);
    }

    float m0 = -1e30f;
    float m1 = -1e30f;
    float l0 = 0.0f;
    float l1 = 0.0f;
    float oacc[8][4];
    #pragma unroll
    for (int dt = 0; dt < 8; dt++)
    {
        #pragma unroll
        for (int x = 0; x < 4; x++) oacc[dt][x] = 0.0f;
    }

    const int NT = TTOT / 64;
    for (int t = 0; t < NT; t++)
    {
        if (t + 1 < NT)
        {
            const u32 so = (u32)((t + 1) & 1) * KV_STAGE;
            #pragma unroll
            for (int l = 0; l < 2; l++)
            {
                int idx = tid + l * 256;
                int r  = idx >> 3;
                int cc = (idx & 7) * 8;
                cp16(sK + so + (u32)(r * 72 + cc) * 2u,
                     Kg + (size_t)((t + 1) * 64 + r) * MD + h * HDIM + cc);
                cp16(sV + so + (u32)(r * 72 + cc) * 2u,
                     Vg + (size_t)((t + 1) * 64 + r) * MD + h * HDIM + cc);
            }
            cp_commit();
            cp_wait1();
        }
        else
        {
            cp_wait0();
        }
        if (tid < 64) smask[tid] = mask[t * 64 + tid];
        __syncthreads();

        const u32 so = (u32)(t & 1) * KV_STAGE;

        float s[8][4];
        #pragma unroll
        for (int jt = 0; jt < 8; jt++)
        {
            #pragma unroll
            for (int x = 0; x < 4; x++) s[jt][x] = 0.0f;
        }
        #pragma unroll
        for (int nb = 0; nb < 4; nb++)
        {
            #pragma unroll
            for (int kf = 0; kf < 4; kf++)
            {
                u32 bf[4];
                int row = nb * 16 + (oct >> 1) * 8 + oj;
                int col = kf * 16 + (oct & 1) * 8;
                ldsm4(bf, sK + so + (u32)(row * 72 + col) * 2u);
                mma16816(s[2 * nb + 0], qa[kf], bf[0], bf[1]);
                mma16816(s[2 * nb + 1], qa[kf], bf[2], bf[3]);
            }
        }

        float mx0 = -1e30f;
        float mx1 = -1e30f;
        #pragma unroll
        for (int jt = 0; jt < 8; jt++)
        {
            float mk0 = smask[jt * 8 + cb];
            float mk1 = smask[jt * 8 + cb + 1];
            s[jt][0] += mk0;
            s[jt][1] += mk1;
            s[jt][2] += mk0;
            s[jt][3] += mk1;
            mx0 = fmaxf(mx0, fmaxf(s[jt][0], s[jt][1]));
            mx1 = fmaxf(mx1, fmaxf(s[jt][2], s[jt][3]));
        }
        mx0 = fmaxf(mx0, __shfl_xor_sync(0xffffffffu, mx0, 1));
        mx0 = fmaxf(mx0, __shfl_xor_sync(0xffffffffu, mx0, 2));
        mx1 = fmaxf(mx1, __shfl_xor_sync(0xffffffffu, mx1, 1));
        mx1 = fmaxf(mx1, __shfl_xor_sync(0xffffffffu, mx1, 2));
        float mn0 = fmaxf(m0, mx0);
        float a0  = __expf(m0 - mn0);
        m0 = mn0;
        float mn1 = fmaxf(m1, mx1);
        float a1  = __expf(m1 - mn1);
        m1 = mn1;

        float rs0 = 0.0f;
        float rs1 = 0.0f;
        #pragma unroll
        for (int jt = 0; jt < 8; jt++)
        {
            s[jt][0] = __expf(s[jt][0] - m0); rs0 += s[jt][0];
            s[jt][1] = __expf(s[jt][1] - m0); rs0 += s[jt][1];
            s[jt][2] = __expf(s[jt][2] - m1); rs1 += s[jt][2];
            s[jt][3] = __expf(s[jt][3] - m1); rs1 += s[jt][3];
        }
        l0 = l0 * a0 + rs0;
        l1 = l1 * a1 + rs1;

        u32 pa[4][4];
        #pragma unroll
        for (int kf = 0; kf < 4; kf++)
        {
            pa[kf][0] = packh2(s[2 * kf + 0][0], s[2 * kf + 0][1]);
            pa[kf][1] = packh2(s[2 * kf + 0][2], s[2 * kf + 0][3]);
            pa[kf][2] = packh2(s[2 * kf + 1][0], s[2 * kf + 1][1]);
            pa[kf][3] = packh2(s[2 * kf + 1][2], s[2 * kf + 1][3]);
        }
        #pragma unroll
        for (int dt = 0; dt < 8; dt++)
        {
            oacc[dt][0] *= a0;
            oacc[dt][1] *= a0;
            oacc[dt][2] *= a1;
            oacc[dt][3] *= a1;
        }
        #pragma unroll
        for (int db = 0; db < 4; db++)
        {
            #pragma unroll
            for (int kf = 0; kf < 4; kf++)
            {
                u32 bf[4];
                int row = kf * 16 + (oct & 1) * 8 + oj;
                int col = db * 16 + (oct >> 1) * 8;
                ldsm4t(bf, sV + so + (u32)(row * 72 + col) * 2u);
                mma16816(oacc[2 * db + 0], pa[kf], bf[0], bf[1]);
                mma16816(oacc[2 * db + 1], pa[kf], bf[2], bf[3]);
            }
        }
        __syncthreads();
    }

    l0 += __shfl_xor_sync(0xffffffffu, l0, 1);
    l0 += __shfl_xor_sync(0xffffffffu, l0, 2);
    l1 += __shfl_xor_sync(0xffffffffu, l1, 1);
    l1 += __shfl_xor_sync(0xffffffffu, l1, 2);
    float inv0 = 1.0f / l0;
    float inv1 = 1.0f / l1;

    #pragma unroll
    for (int dt = 0; dt < 8; dt++)
    {
        int row = bq + warp * 16 + (lane >> 2);
        int col = h * HDIM + dt * 8 + cb;
        *(__half2*)(AO + (size_t)row * MD + col) =
            __floats2half2_rn(oacc[dt][0] * inv0, oacc[dt][1] * inv0);
        *(__half2*)(AO + (size_t)(row + 8) * MD + col) =
            __floats2half2_rn(oacc[dt][2] * inv1, oacc[dt][3] * inv1);
    }
}

// ----------------------------------------------------------------------------
extern "C" void kernel_launch(void* const* d_in, const int* in_sizes, int n_in,
                              void* d_out, int out_size)
{
    const float* hidden = (const float*)d_in[0];
    const float* enc    = (const float*)d_in[1];
    const float* mask   = (const float*)d_in[2];
    const float* qw  = (const float*)d_in[3];
    const float* qb  = (const float*)d_in[4];
    const float* kw  = (const float*)d_in[5];
    const float* kb  = (const float*)d_in[6];
    const float* vw  = (const float*)d_in[7];
    const float* vb  = (const float*)d_in[8];
    const float* nq  = (const float*)d_in[9];
    const float* nk  = (const float*)d_in[10];
    const float* akw = (const float*)d_in[13];
    const float* akb = (const float*)d_in[14];
    const float* avw = (const float*)d_in[15];
    const float* avb = (const float*)d_in[16];
    const float* nak = (const float*)d_in[18];
    const float* ow  = (const float*)d_in[19];
    const float* ob  = (const float*)d_in[20];
    float* outp = (float*)d_out;

    __half* h16 = 0;
    __half* e16 = 0;
    __half* w16 = 0;
    __half* Q16 = 0;
    __half* K16 = 0;
    __half* V16 = 0;
    __half* AO16 = 0;
    cudaGetSymbolAddress((void**)&h16,  g_h16);
    cudaGetSymbolAddress((void**)&e16,  g_e16);
    cudaGetSymbolAddress((void**)&w16,  g_w16);
    cudaGetSymbolAddress((void**)&Q16,  g_Q16);
    cudaGetSymbolAddress((void**)&K16,  g_K16);
    cudaGetSymbolAddress((void**)&V16,  g_V16);
    cudaGetSymbolAddress((void**)&AO16, g_AO16);

    __half* wq16  = w16 + 0 * (size_t)MD * MD;
    __half* wk16  = w16 + 1 * (size_t)MD * MD;
    __half* wv16  = w16 + 2 * (size_t)MD * MD;
    __half* wak16 = w16 + 3 * (size_t)MD * MD;
    __half* wav16 = w16 + 4 * (size_t)MD * MD;
    __half* wo16  = w16 + 5 * (size_t)MD * MD;

    const int nw4 = MD * MD / 4;
    const int nh4 = SHID * MD / 4;
    const int ne4 = SENC * MD / 4;

    CvtJobs jobs;
    jobs.src[0] = hidden;  jobs.dst[0] = h16;   jobs.n4[0] = nh4;
    jobs.src[1] = enc;     jobs.dst[1] = e16;   jobs.n4[1] = ne4;
    jobs.src[2] = qw;      jobs.dst[2] = wq16;  jobs.n4[2] = nw4;
    jobs.src[3] = kw;      jobs.dst[3] = wk16;  jobs.n4[3] = nw4;
    jobs.src[4] = vw;      jobs.dst[4] = wv16;  jobs.n4[4] = nw4;
    jobs.src[5] = akw;     jobs.dst[5] = wak16; jobs.n4[5] = nw4;
    jobs.src[6] = avw;     jobs.dst[6] = wav16; jobs.n4[6] = nw4;
    jobs.src[7] = ow;      jobs.dst[7] = wo16;  jobs.n4[7] = nw4;

    int maxB = (nh4 / 4 + 255) / 256;
    dim3 cgrid(maxB, 8, 1);
    dim3 cblk(256, 1, 1);
    cvt_multi<<<cgrid, cblk>>>(jobs);

    cudaFuncSetAttribute(gemm_f16x, cudaFuncAttributeMaxDynamicSharedMemorySize, G_SMEM);
    cudaFuncSetAttribute(flash16, cudaFuncAttributeMaxDynamicSharedMemorySize, F_SMEM);

    dim3 blk(256, 1, 1);

    // one launch: all 5 projections (Q,K,V hidden + K,V encoder),
    // RMSNorm fused into Q and K epilogues (Q also gets 1/sqrt(64)).
    GemmJobs jP;
    jP.A[0] = h16;  jP.W[0] = wq16;  jP.bias[0] = qb;  jP.normw[0] = nq;
    jP.C[0] = Q16;  jP.M[0] = SHID;  jP.mode[0] = 2;   jP.scale[0] = 0.125f;
    jP.A[1] = h16;  jP.W[1] = wk16;  jP.bias[1] = kb;  jP.normw[1] = nk;
    jP.C[1] = K16;  jP.M[1] = SHID;  jP.mode[1] = 2;   jP.scale[1] = 1.0f;
    jP.A[2] = h16;  jP.W[2] = wv16;  jP.bias[2] = vb;  jP.normw[2] = nq;
    jP.C[2] = V16;  jP.M[2] = SHID;  jP.mode[2] = 1;   jP.scale[2] = 1.0f;
    jP.A[3] = e16;  jP.W[3] = wak16; jP.bias[3] = akb; jP.normw[3] = nak;
    jP.C[3] = K16 + (size_t)SHID * MD;  jP.M[3] = SENC;  jP.mode[3] = 2;  jP.scale[3] = 1.0f;
    jP.A[4] = e16;  jP.W[4] = wav16; jP.bias[4] = avb; jP.normw[4] = nq;
    jP.C[4] = V16 + (size_t)SHID * MD;  jP.M[4] = SENC;  jP.mode[4] = 1;  jP.scale[4] = 1.0f;
    dim3 gP(MD / 128, SHID / 128, 5);
    gemm_f16x<<<gP, blk, G_SMEM>>>(jP, MD, MD);

    // flash attention (HMMA, cp.async double-buffered K/V)
    dim3 gF(SHID / 128, NHEAD, 1);
    flash16<<<gF, blk, F_SMEM>>>(Q16, K16, V16, mask, AO16);

    // output projection -> fp32 d_out
    GemmJobs jO;
    jO.A[0] = AO16;  jO.W[0] = wo16;  jO.bias[0] = ob;  jO.normw[0] = nq;
    jO.C[0] = outp;  jO.M[0] = SHID;  jO.mode[0] = 0;   jO.scale[0] = 1.0f;
    #pragma unroll
    for (int i = 1; i < 5; i++)
    {
        jO.A[i] = AO16;  jO.W[i] = wo16;  jO.bias[i] = ob;  jO.normw[i] = nq;
        jO.C[i] = outp;  jO.M[i] = 0;     jO.mode[i] = 0;   jO.scale[i] = 1.0f;
    }
    dim3 gO(MD / 128, SHID / 128, 1);
    gemm_f16x<<<gO, blk, G_SMEM>>>(jO, MD, MD);
}

// round 10
// speedup vs baseline: 8.9566x; 1.1177x over previous
#include <cuda_runtime.h>
#include <cuda_fp16.h>
#include <stdint.h>
#include <math.h>

typedef unsigned int u32;

#define MD    1536
#define SHID  2048
#define SENC  256
#define TTOT  2304
#define NHEAD 24
#define HDIM  64

// ---------------- scratch (__device__ globals: allocation-free rule) --------
__device__ __half g_h16 [SHID * MD];
__device__ __half g_e16 [SENC * MD];
__device__ __half g_w16 [6 * MD * MD];
__device__ __half g_Q16 [SHID * MD];
__device__ __half g_K16 [TTOT * MD];
__device__ __half g_V16 [TTOT * MD];
__device__ __half g_AO16[SHID * MD];

// ---------------- warp-mma helpers ------------------------------------------
__device__ __forceinline__ void ldsm4(u32* r, u32 addr)
{
    asm volatile("ldmatrix.sync.aligned.m8n8.x4.shared.b16 {%0,%1,%2,%3}, [%4];"
                 : "=r"(r[0]), "=r"(r[1]), "=r"(r[2]), "=r"(r[3]) : "r"(addr));
}

__device__ __forceinline__ void ldsm4t(u32* r, u32 addr)
{
    asm volatile("ldmatrix.sync.aligned.m8n8.x4.trans.shared.b16 {%0,%1,%2,%3}, [%4];"
                 : "=r"(r[0]), "=r"(r[1]), "=r"(r[2]), "=r"(r[3]) : "r"(addr));
}

__device__ __forceinline__ void mma16816(float* c, const u32* a, u32 b0, u32 b1)
{
    asm volatile(
        "mma.sync.aligned.m16n8k16.row.col.f32.f16.f16.f32 "
        "{%0,%1,%2,%3}, {%4,%5,%6,%7}, {%8,%9}, {%0,%1,%2,%3};"
        : "+f"(c[0]), "+f"(c[1]), "+f"(c[2]), "+f"(c[3])
        : "r"(a[0]), "r"(a[1]), "r"(a[2]), "r"(a[3]), "r"(b0), "r"(b1));
}

__device__ __forceinline__ u32 packh2(float x, float y)
{
    __half2 h = __floats2half2_rn(x, y);
    return *reinterpret_cast<u32*>(&h);
}

__device__ __forceinline__ void cp16(u32 smem_dst, const void* gmem_src)
{
    asm volatile("cp.async.cg.shared.global [%0], [%1], 16;"
                 :: "r"(smem_dst), "l"(gmem_src));
}

__device__ __forceinline__ void cp_commit()
{
    asm volatile("cp.async.commit_group;");
}

__device__ __forceinline__ void cp_wait1()
{
    asm volatile("cp.async.wait_group 1;");
}

__device__ __forceinline__ void cp_wait0()
{
    asm volatile("cp.async.wait_group 0;");
}

// ---------------- merged fp32 -> fp16 convert (one launch, 8 segments) -----
struct CvtJobs
{
    const float* src[8];
    __half*      dst[8];
    int          n4[8];
};

__global__ __launch_bounds__(256) void cvt_multi(CvtJobs jobs)
{
    int seg = blockIdx.y;
    const float* __restrict__ src = jobs.src[seg];
    __half* __restrict__ dst = jobs.dst[seg];
    int n4 = jobs.n4[seg];
    int i0 = (blockIdx.x * 256 + threadIdx.x) * 4;
    if (i0 >= n4) return;
    #pragma unroll
    for (int j = 0; j < 4; j++)
    {
        int i = i0 + j;
        float4 v = ((const float4*)src)[i];
        ((__half2*)dst)[2 * i + 0] = __floats2half2_rn(v.x, v.y);
        ((__half2*)dst)[2 * i + 1] = __floats2half2_rn(v.z, v.w);
    }
}

// ---------------- multi-job fp16 GEMM, 64x64 warp tiles ---------------------
// C[z] = f( A[z][M,K] @ W[z][N,K]^T + bias[z] )
// mode 0: f32 out, 1: f16 out, 2: f16 out with per-64-col-head RMSNorm*scale.
// BM=128, BN=128, BK=32, 128 threads (4 warps: 2m x 2n), warp tile 64x64.
// 3-stage cp.async pipeline (dynamic smem). A head (64 cols) == one warp's
// n-range, so the fused RMSNorm reduction is warp-local (quad shuffles).
struct GemmJobs
{
    const __half* A[5];
    const __half* W[5];
    const float*  bias[5];
    const float*  normw[5];
    void*         C[5];
    int           M[5];
    int           mode[5];
    float         scale[5];
};

#define GSTG_B   10240            // one stage of one matrix: 128*40 halves
#define GB_OFF   30720            // 3 stages of A
#define G_SMEM   61440

__global__ __launch_bounds__(128) void gemm_f16x(GemmJobs job, int N, int K)
{
    extern __shared__ __align__(16) char gsm[];
    const int z = blockIdx.z;
    const int bm = blockIdx.y * 128;
    if (bm >= job.M[z]) return;
    const __half* __restrict__ A = job.A[z];
    const __half* __restrict__ W = job.W[z];
    const float* __restrict__ bias = job.bias[z];
    const float* __restrict__ normw = job.normw[z];
    void* Cout = job.C[z];
    const int mode = job.mode[z];
    const float nscale = job.scale[z];

    const int bn = blockIdx.x * 128;
    const int tid  = threadIdx.x;
    const int lane = tid & 31;
    const int warp = tid >> 5;      // 0..3
    const int wm  = warp & 1;       // 2 warp-rows of 64
    const int wn  = warp >> 1;      // 2 warp-cols of 64
    const int oct = lane >> 3;
    const int oj  = lane & 7;

    const u32 sA = (u32)__cvta_generic_to_shared(gsm);
    const u32 sB = sA + GB_OFF;

    float acc[4][8][4];
    #pragma unroll
    for (int mi = 0; mi < 4; mi++)
        #pragma unroll
        for (int ni = 0; ni < 8; ni++)
            #pragma unroll
            for (int x = 0; x < 4; x++) acc[mi][ni][x] = 0.0f;

    const int KT = K >> 5;

    // prologue: tiles 0, 1
    #pragma unroll
    for (int pt = 0; pt < 2; pt++)
    {
        const u32 so = (u32)pt * GSTG_B;
        #pragma unroll
        for (int l = 0; l < 4; l++)
        {
            int idx = tid + l * 128;
            int row = idx >> 2;
            int ch  = idx & 3;
            u32 d = so + (u32)(row * 40 + ch * 8) * 2u;
            cp16(sA + d, A + (size_t)(bm + row) * K + pt * 32 + ch * 8);
            cp16(sB + d, W + (size_t)(bn + row) * K + pt * 32 + ch * 8);
        }
        cp_commit();
    }

    for (int kt = 0; kt < KT; kt++)
    {
        if (kt == KT - 1) cp_wait0(); else cp_wait1();
        __syncthreads();

        if (kt + 2 < KT)
        {
            const int nt = kt + 2;
            const u32 so = (u32)(nt % 3) * GSTG_B;
            #pragma unroll
            for (int l = 0; l < 4; l++)
            {
                int idx = tid + l * 128;
                int row = idx >> 2;
                int ch  = idx & 3;
                u32 d = so + (u32)(row * 40 + ch * 8) * 2u;
                cp16(sA + d, A + (size_t)(bm + row) * K + nt * 32 + ch * 8);
                cp16(sB + d, W + (size_t)(bn + row) * K + nt * 32 + ch * 8);
            }
            cp_commit();
        }

        const u32 so = (u32)(kt % 3) * GSTG_B;
        #pragma unroll
        for (int ks = 0; ks < 2; ks++)
        {
            const int ksh = ks * 16;
            u32 af[4][4];
            #pragma unroll
            for (int mi = 0; mi < 4; mi++)
            {
                int row = wm * 64 + mi * 16 + (oct & 1) * 8 + oj;
                int col = ksh + (oct >> 1) * 8;
                ldsm4(af[mi], sA + so + (u32)(row * 40 + col) * 2u);
            }
            u32 bf[4][4];
            #pragma unroll
            for (int nb = 0; nb < 4; nb++)
            {
                int row = wn * 64 + nb * 16 + (oct >> 1) * 8 + oj;
                int col = ksh + (oct & 1) * 8;
                ldsm4(bf[nb], sB + so + (u32)(row * 40 + col) * 2u);
            }
            #pragma unroll
            for (int mi = 0; mi < 4; mi++)
            {
                #pragma unroll
                for (int nb = 0; nb < 4; nb++)
                {
                    mma16816(acc[mi][2 * nb + 0], af[mi], bf[nb][0], bf[nb][1]);
                    mma16816(acc[mi][2 * nb + 1], af[mi], bf[nb][2], bf[nb][3]);
                }
            }
        }
    }

    // ---- epilogue (no barriers needed) ----
    #pragma unroll
    for (int ni = 0; ni < 8; ni++)
    {
        int col = bn + wn * 64 + ni * 8 + (lane & 3) * 2;
        float b0 = bias[col];
        float b1 = bias[col + 1];
        #pragma unroll
        for (int mi = 0; mi < 4; mi++)
        {
            acc[mi][ni][0] += b0;
            acc[mi][ni][1] += b1;
            acc[mi][ni][2] += b0;
            acc[mi][ni][3] += b1;
        }
    }

    if (mode == 2)
    {
        // fused per-head RMSNorm: head = this warp's 64 cols; row sums are
        // warp-local (quad lanes hold 8-col strips of the same row).
        __half* C = (__half*)Cout;
        #pragma unroll
        for (int mi = 0; mi < 4; mi++)
        {
            float s0 = 0.0f;
            float s1 = 0.0f;
            #pragma unroll
            for (int ni = 0; ni < 8; ni++)
            {
                s0 += acc[mi][ni][0] * acc[mi][ni][0] + acc[mi][ni][1] * acc[mi][ni][1];
                s1 += acc[mi][ni][2] * acc[mi][ni][2] + acc[mi][ni][3] * acc[mi][ni][3];
            }
            s0 += __shfl_xor_sync(0xffffffffu, s0, 1);
            s0 += __shfl_xor_sync(0xffffffffu, s0, 2);
            s1 += __shfl_xor_sync(0xffffffffu, s1, 1);
            s1 += __shfl_xor_sync(0xffffffffu, s1, 2);
            float rs0 = rsqrtf(s0 * (1.0f / HDIM) + 1e-6f) * nscale;
            float rs1 = rsqrtf(s1 * (1.0f / HDIM) + 1e-6f) * nscale;
            int row = bm + wm * 64 + mi * 16 + (lane >> 2);
            #pragma unroll
            for (int ni = 0; ni < 8; ni++)
            {
                int wcol = ni * 8 + (lane & 3) * 2;
                float w0 = normw[wcol];
                float w1 = normw[wcol + 1];
                int col = bn + wn * 64 + wcol;
                *(__half2*)(C + (size_t)row * N + col) =
                    __floats2half2_rn(acc[mi][ni][0] * rs0 * w0, acc[mi][ni][1] * rs0 * w1);
                *(__half2*)(C + (size_t)(row + 8) * N + col) =
                    __floats2half2_rn(acc[mi][ni][2] * rs1 * w0, acc[mi][ni][3] * rs1 * w1);
            }
        }
    }
    else if (mode == 1)
    {
        __half* C = (__half*)Cout;
        #pragma unroll
        for (int mi = 0; mi < 4; mi++)
        {
            int row = bm + wm * 64 + mi * 16 + (lane >> 2);
            #pragma unroll
            for (int ni = 0; ni < 8; ni++)
            {
                int col = bn + wn * 64 + ni * 8 + (lane & 3) * 2;
                *(__half2*)(C + (size_t)row * N + col) =
                    __floats2half2_rn(acc[mi][ni][0], acc[mi][ni][1]);
                *(__half2*)(C + (size_t)(row + 8) * N + col) =
                    __floats2half2_rn(acc[mi][ni][2], acc[mi][ni][3]);
            }
        }
    }
    else
    {
        float* C = (float*)Cout;
        #pragma unroll
        for (int mi = 0; mi < 4; mi++)
        {
            int row = bm + wm * 64 + mi * 16 + (lane >> 2);
            #pragma unroll
            for (int ni = 0; ni < 8; ni++)
            {
                int col = bn + wn * 64 + ni * 8 + (lane & 3) * 2;
                *(float2*)(C + (size_t)row * N + col) =
                    make_float2(acc[mi][ni][0], acc[mi][ni][1]);
                *(float2*)(C + (size_t)(row + 8) * N + col) =
                    make_float2(acc[mi][ni][2], acc[mi][ni][3]);
            }
        }
    }
}

// ---------------- fp16 flash attention (tensor core, cp.async K/V) ----------
#define FQ_OFF   0
#define FK_OFF   18432
#define FV_OFF   36864
#define FM_OFF   55296
#define F_SMEM   64512
#define KV_STAGE 9216

__global__ __launch_bounds__(256) void flash16(
    const __half* __restrict__ Qg, const __half* __restrict__ Kg,
    const __half* __restrict__ Vg, const float* __restrict__ mask,
    __half* __restrict__ AO)
{
    extern __shared__ __align__(16) char fsm[];
    __half* Qs = (__half*)(fsm + FQ_OFF);
    float* smask = (float*)(fsm + FM_OFF);

    const int h  = blockIdx.y;
    const int bq = blockIdx.x * 128;
    const int tid  = threadIdx.x;
    const int lane = tid & 31;
    const int warp = tid >> 5;
    const int oct = lane >> 3;
    const int oj  = lane & 7;
    const int cb  = (lane & 3) * 2;

    const u32 smemBase = (u32)__cvta_generic_to_shared(fsm);
    const u32 sQ = smemBase + FQ_OFF;
    const u32 sK = smemBase + FK_OFF;
    const u32 sV = smemBase + FV_OFF;

    #pragma unroll
    for (int l = 0; l < 4; l++)
    {
        int idx = tid + l * 256;
        int r  = idx >> 3;
        int cc = (idx & 7) * 8;
        *(int4*)(Qs + r * 72 + cc) =
            *(const int4*)(Qg + (size_t)(bq + r) * MD + h * HDIM + cc);
    }
    // whole mask (2304 floats) once
    for (int i = tid; i < TTOT; i += 256) smask[i] = mask[i];

    {
        #pragma unroll
        for (int l = 0; l < 2; l++)
        {
            int idx = tid + l * 256;
            int r  = idx >> 3;
            int cc = (idx & 7) * 8;
            cp16(sK + (u32)(r * 72 + cc) * 2u, Kg + (size_t)r * MD + h * HDIM + cc);
            cp16(sV + (u32)(r * 72 + cc) * 2u, Vg + (size_t)r * MD + h * HDIM + cc);
        }
        cp_commit();
    }

    __syncthreads();
    u32 qa[4][4];
    #pragma unroll
    for (int kf = 0; kf < 4; kf++)
    {
        int row = warp * 16 + (oct & 1) * 8 + oj;
        int col = kf * 16 + (oct >> 1) * 8;
        ldsm4(qa[kf], sQ + (u32)(row * 72 + col) * 2u);
    }

    float m0 = -1e30f;
    float m1 = -1e30f;
    float l0 = 0.0f;
    float l1 = 0.0f;
    float oacc[8][4];
    #pragma unroll
    for (int dt = 0; dt < 8; dt++)
    {
        #pragma unroll
        for (int x = 0; x < 4; x++) oacc[dt][x] = 0.0f;
    }

    const int NT = TTOT / 64;
    for (int t = 0; t < NT; t++)
    {
        if (t + 1 < NT)
        {
            const u32 so = (u32)((t + 1) & 1) * KV_STAGE;
            #pragma unroll
            for (int l = 0; l < 2; l++)
            {
                int idx = tid + l * 256;
                int r  = idx >> 3;
                int cc = (idx & 7) * 8;
                cp16(sK + so + (u32)(r * 72 + cc) * 2u,
                     Kg + (size_t)((t + 1) * 64 + r) * MD + h * HDIM + cc);
                cp16(sV + so + (u32)(r * 72 + cc) * 2u,
                     Vg + (size_t)((t + 1) * 64 + r) * MD + h * HDIM + cc);
            }
            cp_commit();
            cp_wait1();
        }
        else
        {
            cp_wait0();
        }
        __syncthreads();

        const u32 so = (u32)(t & 1) * KV_STAGE;

        float s[8][4];
        #pragma unroll
        for (int jt = 0; jt < 8; jt++)
        {
            #pragma unroll
            for (int x = 0; x < 4; x++) s[jt][x] = 0.0f;
        }
        #pragma unroll
        for (int nb = 0; nb < 4; nb++)
        {
            #pragma unroll
            for (int kf = 0; kf < 4; kf++)
            {
                u32 bf[4];
                int row = nb * 16 + (oct >> 1) * 8 + oj;
                int col = kf * 16 + (oct & 1) * 8;
                ldsm4(bf, sK + so + (u32)(row * 72 + col) * 2u);
                mma16816(s[2 * nb + 0], qa[kf], bf[0], bf[1]);
                mma16816(s[2 * nb + 1], qa[kf], bf[2], bf[3]);
            }
        }

        float mx0 = -1e30f;
        float mx1 = -1e30f;
        #pragma unroll
        for (int jt = 0; jt < 8; jt++)
        {
            float mk0 = smask[t * 64 + jt * 8 + cb];
            float mk1 = smask[t * 64 + jt * 8 + cb + 1];
            s[jt][0] += mk0;
            s[jt][1] += mk1;
            s[jt][2] += mk0;
            s[jt][3] += mk1;
            mx0 = fmaxf(mx0, fmaxf(s[jt][0], s[jt][1]));
            mx1 = fmaxf(mx1, fmaxf(s[jt][2], s[jt][3]));
        }
        mx0 = fmaxf(mx0, __shfl_xor_sync(0xffffffffu, mx0, 1));
        mx0 = fmaxf(mx0, __shfl_xor_sync(0xffffffffu, mx0, 2));
        mx1 = fmaxf(mx1, __shfl_xor_sync(0xffffffffu, mx1, 1));
        mx1 = fmaxf(mx1, __shfl_xor_sync(0xffffffffu, mx1, 2));
        float mn0 = fmaxf(m0, mx0);
        float a0  = __expf(m0 - mn0);
        m0 = mn0;
        float mn1 = fmaxf(m1, mx1);
        float a1  = __expf(m1 - mn1);
        m1 = mn1;

        float rs0 = 0.0f;
        float rs1 = 0.0f;
        #pragma unroll
        for (int jt = 0; jt < 8; jt++)
        {
            s[jt][0] = __expf(s[jt][0] - m0); rs0 += s[jt][0];
            s[jt][1] = __expf(s[jt][1] - m0); rs0 += s[jt][1];
            s[jt][2] = __expf(s[jt][2] - m1); rs1 += s[jt][2];
            s[jt][3] = __expf(s[jt][3] - m1); rs1 += s[jt][3];
        }
        l0 = l0 * a0 + rs0;
        l1 = l1 * a1 + rs1;

        u32 pa[4][4];
        #pragma unroll
        for (int kf = 0; kf < 4; kf++)
        {
            pa[kf][0] = packh2(s[2 * kf + 0][0], s[2 * kf + 0][1]);
            pa[kf][1] = packh2(s[2 * kf + 0][2], s[2 * kf + 0][3]);
            pa[kf][2] = packh2(s[2 * kf + 1][0], s[2 * kf + 1][1]);
            pa[kf][3] = packh2(s[2 * kf + 1][2], s[2 * kf + 1][3]);
        }
        #pragma unroll
        for (int dt = 0; dt < 8; dt++)
        {
            oacc[dt][0] *= a0;
            oacc[dt][1] *= a0;
            oacc[dt][2] *= a1;
            oacc[dt][3] *= a1;
        }
        #pragma unroll
        for (int db = 0; db < 4; db++)
        {
            #pragma unroll
            for (int kf = 0; kf < 4; kf++)
            {
                u32 bf[4];
                int row = kf * 16 + (oct & 1) * 8 + oj;
                int col = db * 16 + (oct >> 1) * 8;
                ldsm4t(bf, sV + so + (u32)(row * 72 + col) * 2u);
                mma16816(oacc[2 * db + 0], pa[kf], bf[0], bf[1]);
                mma16816(oacc[2 * db + 1], pa[kf], bf[2], bf[3]);
            }
        }
        __syncthreads();
    }

    l0 += __shfl_xor_sync(0xffffffffu, l0, 1);
    l0 += __shfl_xor_sync(0xffffffffu, l0, 2);
    l1 += __shfl_xor_sync(0xffffffffu, l1, 1);
    l1 += __shfl_xor_sync(0xffffffffu, l1, 2);
    float inv0 = 1.0f / l0;
    float inv1 = 1.0f / l1;

    #pragma unroll
    for (int dt = 0; dt < 8; dt++)
    {
        int row = bq + warp * 16 + (lane >> 2);
        int col = h * HDIM + dt * 8 + cb;
        *(__half2*)(AO + (size_t)row * MD + col) =
            __floats2half2_rn(oacc[dt][0] * inv0, oacc[dt][1] * inv0);
        *(__half2*)(AO + (size_t)(row + 8) * MD + col) =
            __floats2half2_rn(oacc[dt][2] * inv1, oacc[dt][3] * inv1);
    }
}

// ----------------------------------------------------------------------------
extern "C" void kernel_launch(void* const* d_in, const int* in_sizes, int n_in,
                              void* d_out, int out_size)
{
    const float* hidden = (const float*)d_in[0];
    const float* enc    = (const float*)d_in[1];
    const float* mask   = (const float*)d_in[2];
    const float* qw  = (const float*)d_in[3];
    const float* qb  = (const float*)d_in[4];
    const float* kw  = (const float*)d_in[5];
    const float* kb  = (const float*)d_in[6];
    const float* vw  = (const float*)d_in[7];
    const float* vb  = (const float*)d_in[8];
    const float* nq  = (const float*)d_in[9];
    const float* nk  = (const float*)d_in[10];
    const float* akw = (const float*)d_in[13];
    const float* akb = (const float*)d_in[14];
    const float* avw = (const float*)d_in[15];
    const float* avb = (const float*)d_in[16];
    const float* nak = (const float*)d_in[18];
    const float* ow  = (const float*)d_in[19];
    const float* ob  = (const float*)d_in[20];
    float* outp = (float*)d_out;

    __half* h16 = 0;
    __half* e16 = 0;
    __half* w16 = 0;
    __half* Q16 = 0;
    __half* K16 = 0;
    __half* V16 = 0;
    __half* AO16 = 0;
    cudaGetSymbolAddress((void**)&h16,  g_h16);
    cudaGetSymbolAddress((void**)&e16,  g_e16);
    cudaGetSymbolAddress((void**)&w16,  g_w16);
    cudaGetSymbolAddress((void**)&Q16,  g_Q16);
    cudaGetSymbolAddress((void**)&K16,  g_K16);
    cudaGetSymbolAddress((void**)&V16,  g_V16);
    cudaGetSymbolAddress((void**)&AO16, g_AO16);

    __half* wq16  = w16 + 0 * (size_t)MD * MD;
    __half* wk16  = w16 + 1 * (size_t)MD * MD;
    __half* wv16  = w16 + 2 * (size_t)MD * MD;
    __half* wak16 = w16 + 3 * (size_t)MD * MD;
    __half* wav16 = w16 + 4 * (size_t)MD * MD;
    __half* wo16  = w16 + 5 * (size_t)MD * MD;

    const int nw4 = MD * MD / 4;
    const int nh4 = SHID * MD / 4;
    const int ne4 = SENC * MD / 4;

    CvtJobs jobs;
    jobs.src[0] = hidden;  jobs.dst[0] = h16;   jobs.n4[0] = nh4;
    jobs.src[1] = enc;     jobs.dst[1] = e16;   jobs.n4[1] = ne4;
    jobs.src[2] = qw;      jobs.dst[2] = wq16;  jobs.n4[2] = nw4;
    jobs.src[3] = kw;      jobs.dst[3] = wk16;  jobs.n4[3] = nw4;
    jobs.src[4] = vw;      jobs.dst[4] = wv16;  jobs.n4[4] = nw4;
    jobs.src[5] = akw;     jobs.dst[5] = wak16; jobs.n4[5] = nw4;
    jobs.src[6] = avw;     jobs.dst[6] = wav16; jobs.n4[6] = nw4;
    jobs.src[7] = ow;      jobs.dst[7] = wo16;  jobs.n4[7] = nw4;

    int maxB = (nh4 / 4 + 255) / 256;
    dim3 cgrid(maxB, 8, 1);
    dim3 cblk(256, 1, 1);
    cvt_multi<<<cgrid, cblk>>>(jobs);

    cudaFuncSetAttribute(gemm_f16x, cudaFuncAttributeMaxDynamicSharedMemorySize, G_SMEM);
    cudaFuncSetAttribute(flash16, cudaFuncAttributeMaxDynamicSharedMemorySize, F_SMEM);

    dim3 blk128(128, 1, 1);

    // one launch: all 5 projections (Q,K,V hidden + K,V encoder),
    // RMSNorm fused into Q and K epilogues (Q also gets 1/sqrt(64)).
    GemmJobs jP;
    jP.A[0] = h16;  jP.W[0] = wq16;  jP.bias[0] = qb;  jP.normw[0] = nq;
    jP.C[0] = Q16;  jP.M[0] = SHID;  jP.mode[0] = 2;   jP.scale[0] = 0.125f;
    jP.A[1] = h16;  jP.W[1] = wk16;  jP.bias[1] = kb;  jP.normw[1] = nk;
    jP.C[1] = K16;  jP.M[1] = SHID;  jP.mode[1] = 2;   jP.scale[1] = 1.0f;
    jP.A[2] = h16;  jP.W[2] = wv16;  jP.bias[2] = vb;  jP.normw[2] = nq;
    jP.C[2] = V16;  jP.M[2] = SHID;  jP.mode[2] = 1;   jP.scale[2] = 1.0f;
    jP.A[3] = e16;  jP.W[3] = wak16; jP.bias[3] = akb; jP.normw[3] = nak;
    jP.C[3] = K16 + (size_t)SHID * MD;  jP.M[3] = SENC;  jP.mode[3] = 2;  jP.scale[3] = 1.0f;
    jP.A[4] = e16;  jP.W[4] = wav16; jP.bias[4] = avb; jP.normw[4] = nq;
    jP.C[4] = V16 + (size_t)SHID * MD;  jP.M[4] = SENC;  jP.mode[4] = 1;  jP.scale[4] = 1.0f;
    dim3 gP(MD / 128, SHID / 128, 5);
    gemm_f16x<<<gP, blk128, G_SMEM>>>(jP, MD, MD);

    // flash attention (HMMA, cp.async double-buffered K/V)
    dim3 gF(SHID / 128, NHEAD, 1);
    dim3 fblk(256, 1, 1);
    flash16<<<gF, fblk, F_SMEM>>>(Q16, K16, V16, mask, AO16);

    // output projection -> fp32 d_out
    GemmJobs jO;
    jO.A[0] = AO16;  jO.W[0] = wo16;  jO.bias[0] = ob;  jO.normw[0] = nq;
    jO.C[0] = outp;  jO.M[0] = SHID;  jO.mode[0] = 0;   jO.scale[0] = 1.0f;
    #pragma unroll
    for (int i = 1; i < 5; i++)
    {
        jO.A[i] = AO16;  jO.W[i] = wo16;  jO.bias[i] = ob;  jO.normw[i] = nq;
        jO.C[i] = outp;  jO.M[i] = 0;     jO.mode[i] = 0;   jO.scale[i] = 1.0f;
    }
    dim3 gO(MD / 128, SHID / 128, 1);
    gemm_f16x<<<gO, blk128, G_SMEM>>>(jO, MD, MD);
}